// round 6
// baseline (speedup 1.0000x reference)
#include <cuda_runtime.h>
#include <math_constants.h>

#define B_   16
#define N_   4096
#define NP_  1024
#define NS_  32
#define NROWS 524288   // B_*NP_*NS_

// ------------------------- static device scratch (no allocation) -------------------------
__device__ __align__(16) float g_newxyz[B_*NP_*3];
__device__ int   g_knn[B_*NP_*NS_];
__device__ __align__(16) float g_Y1[33554432];   // 524288 x 64
__device__ __align__(16) float g_Y2[33554432];   // 524288 x 64
__device__ __align__(16) float g_Y3[67108864];   // 524288 x 128
__device__ float g_psum[128*128];
__device__ float g_psq [128*128];
__device__ float g_scale[3][128];
__device__ float g_shift[3][128];
__device__ __align__(16) float g_wt0[67*64];
__device__ __align__(16) float g_wt1[64*64];
__device__ __align__(16) float g_wt2[64*128];

// ------------------------- init: transpose weights to [K][OC] -------------------------
__global__ void k_init(const float* __restrict__ w0, const float* __restrict__ w1,
                       const float* __restrict__ w2) {
    int t = blockIdx.x * blockDim.x + threadIdx.x;
    int stride = gridDim.x * blockDim.x;
    for (int l = t; l < 64*67; l += stride) { int oc = l / 67, k = l - oc*67; g_wt0[k*64 + oc] = w0[l]; }
    for (int l = t; l < 64*64; l += stride) { int oc = l >> 6, k = l & 63;    g_wt1[k*64 + oc] = w1[l]; }
    for (int l = t; l < 128*64; l += stride){ int oc = l >> 6, k = l & 63;    g_wt2[k*128 + oc] = w2[l]; }
}

// ------------------------- FPS: one block per batch, exact JAX arithmetic ----------------
__global__ __launch_bounds__(1024)
void k_fps(const float* __restrict__ xyz, float* __restrict__ out) {
    int b = blockIdx.x, t = threadIdx.x;
    const float* X = xyz + (size_t)b * N_ * 3;
    float px[4], py[4], pz[4], dd[4];
#pragma unroll
    for (int j = 0; j < 4; j++) {
        int n = t*4 + j;
        px[j] = X[n*3]; py[j] = X[n*3+1]; pz[j] = X[n*3+2];
        dd[j] = 1e10f;
    }
    __shared__ float cx, cy, cz;
    __shared__ float wv[32]; __shared__ int wi[32];
    __shared__ int sfar;
    if (t == 0) { cx = px[0]; cy = py[0]; cz = pz[0]; }
    __syncthreads();
    float* nx = g_newxyz + (size_t)b * NP_ * 3;
    float* ox = out + (size_t)b * NP_ * 3;

    for (int i = 0; i < NP_; i++) {
        float ccx = cx, ccy = cy, ccz = cz;
        if (t == 0) {
            nx[i*3] = ccx; nx[i*3+1] = ccy; nx[i*3+2] = ccz;
            ox[i*3] = ccx; ox[i*3+1] = ccy; ox[i*3+2] = ccz;
        }
        float bv = -1.0f; int bi = 0;
#pragma unroll
        for (int j = 0; j < 4; j++) {
            float dx = __fsub_rn(px[j], ccx);
            float dy = __fsub_rn(py[j], ccy);
            float dz = __fsub_rn(pz[j], ccz);
            float d  = __fadd_rn(__fadd_rn(__fmul_rn(dx,dx), __fmul_rn(dy,dy)), __fmul_rn(dz,dz));
            dd[j] = fminf(dd[j], d);
            if (dd[j] > bv) { bv = dd[j]; bi = t*4 + j; }   // strict > keeps lowest idx on tie
        }
#pragma unroll
        for (int off = 16; off; off >>= 1) {
            float ov = __shfl_down_sync(0xffffffffu, bv, off);
            int   oi = __shfl_down_sync(0xffffffffu, bi, off);
            if (ov > bv || (ov == bv && oi < bi)) { bv = ov; bi = oi; }
        }
        if ((t & 31) == 0) { wv[t>>5] = bv; wi[t>>5] = bi; }
        __syncthreads();
        if (t < 32) {
            bv = wv[t]; bi = wi[t];
#pragma unroll
            for (int off = 16; off; off >>= 1) {
                float ov = __shfl_down_sync(0xffffffffu, bv, off);
                int   oi = __shfl_down_sync(0xffffffffu, bi, off);
                if (ov > bv || (ov == bv && oi < bi)) { bv = ov; bi = oi; }
            }
            if (t == 0) sfar = bi;
        }
        __syncthreads();
        int f = sfar;
        if ((f >> 2) == t) {
            int j = f & 3;
            cx = px[j]; cy = py[j]; cz = pz[j];
        }
        __syncthreads();
    }
}

// ------------------------- kNN: block per query, 32-round extraction ----------------------
__global__ __launch_bounds__(128)
void k_knn(const float* __restrict__ xyz) {
    int q = blockIdx.x;              // b*1024 + m
    int b = q >> 10;
    int t = threadIdx.x;
    const float* X = xyz + (size_t)b * N_ * 3;
    const float* Q = g_newxyz + (size_t)q * 3;
    float qx = Q[0], qy = Q[1], qz = Q[2];
    float sqn = __fadd_rn(__fadd_rn(__fmul_rn(qx,qx), __fmul_rn(qy,qy)), __fmul_rn(qz,qz));

    __shared__ float sd[N_];
    float bv = CUDART_INF_F; int bi = 0x7fffffff;
#pragma unroll 4
    for (int i = 0; i < 32; i++) {
        int n = i*128 + t;
        float x = X[n*3], y = X[n*3+1], z = X[n*3+2];
        float sq  = __fadd_rn(__fadd_rn(__fmul_rn(x,x), __fmul_rn(y,y)), __fmul_rn(z,z));
        float dot = __fadd_rn(__fadd_rn(__fmul_rn(qx,x), __fmul_rn(qy,y)), __fmul_rn(qz,z));
        float d2  = __fsub_rn(__fadd_rn(sqn, sq), __fmul_rn(2.0f, dot));
        sd[n] = d2;
        if (d2 < bv || (d2 == bv && n < bi)) { bv = d2; bi = n; }
    }
    __shared__ float wv[4]; __shared__ int wi[4]; __shared__ int swin;
    int* KO = g_knn + (size_t)q * NS_;

    for (int r = 0; r < NS_; r++) {
        float v = bv; int ix = bi;
#pragma unroll
        for (int off = 16; off; off >>= 1) {
            float ov = __shfl_down_sync(0xffffffffu, v, off);
            int   oi = __shfl_down_sync(0xffffffffu, ix, off);
            if (ov < v || (ov == v && oi < ix)) { v = ov; ix = oi; }
        }
        if ((t & 31) == 0) { wv[t>>5] = v; wi[t>>5] = ix; }
        __syncthreads();
        if (t == 0) {
            v = wv[0]; ix = wi[0];
#pragma unroll
            for (int w = 1; w < 4; w++)
                if (wv[w] < v || (wv[w] == v && wi[w] < ix)) { v = wv[w]; ix = wi[w]; }
            swin = ix;
            KO[r] = ix;
        }
        __syncthreads();
        int win = swin;
        if ((win & 127) == t) {      // owner rescans its private column of sd
            sd[win] = CUDART_INF_F;
            bv = CUDART_INF_F; bi = 0x7fffffff;
            for (int i = 0; i < 32; i++) {
                int n = i*128 + t; float d = sd[n];
                if (d < bv || (d == bv && n < bi)) { bv = d; bi = n; }
            }
        }
    }
}

// ------------------------- GEMM layer 1: fused gather, K=67 -> OC=64 ----------------------
__global__ __launch_bounds__(128)
void k_gemm1(const float* __restrict__ xyz, const float* __restrict__ pts) {
    __shared__ __align__(16) float ws[67*64];
    int t = threadIdx.x;
    for (int i = t; i < 67*64; i += 128) ws[i] = g_wt0[i];
    __syncthreads();

    size_t r = (size_t)blockIdx.x * 128 + t;
    int b  = (int)(r >> 15);
    int bm = (int)(r >> 5);
    int j  = g_knn[r];
    const float* P = xyz + ((size_t)b * N_ + j) * 3;
    const float* Q = g_newxyz + (size_t)bm * 3;
    float f0 = P[0] - Q[0], f1 = P[1] - Q[1], f2 = P[2] - Q[2];

    float acc[64];
#pragma unroll
    for (int o = 0; o < 64; o++) acc[o] = 0.f;

    float f3[3] = {f0, f1, f2};
#pragma unroll
    for (int k = 0; k < 3; k++) {
        float xk = f3[k];
        const float* wr = &ws[k*64];
#pragma unroll
        for (int o = 0; o < 64; o += 4) {
            float4 w = *(const float4*)(wr + o);
            acc[o]   = fmaf(xk, w.x, acc[o]);
            acc[o+1] = fmaf(xk, w.y, acc[o+1]);
            acc[o+2] = fmaf(xk, w.z, acc[o+2]);
            acc[o+3] = fmaf(xk, w.w, acc[o+3]);
        }
    }
    const float4* prow = (const float4*)(pts + ((size_t)b * N_ + j) * 64);
#pragma unroll 1
    for (int kc = 0; kc < 16; kc++) {
        float4 xv = __ldg(&prow[kc]);
        const float* wr = &ws[(3 + kc*4) * 64];
        float xs[4] = {xv.x, xv.y, xv.z, xv.w};
#pragma unroll
        for (int kk = 0; kk < 4; kk++) {
            float xk = xs[kk];
#pragma unroll
            for (int o = 0; o < 64; o += 4) {
                float4 w = *(const float4*)(wr + kk*64 + o);
                acc[o]   = fmaf(xk, w.x, acc[o]);
                acc[o+1] = fmaf(xk, w.y, acc[o+1]);
                acc[o+2] = fmaf(xk, w.z, acc[o+2]);
                acc[o+3] = fmaf(xk, w.w, acc[o+3]);
            }
        }
    }
    float4* Y = (float4*)(g_Y1 + r * 64);
#pragma unroll
    for (int o = 0; o < 64; o += 4) {
        float4 v = {acc[o], acc[o+1], acc[o+2], acc[o+3]};
        Y[o >> 2] = v;
    }
}

// ------------------------- GEMM layer 2: BN+ReLU(Y1) @ W1, K=64 -> OC=64 -------------------
__global__ __launch_bounds__(128)
void k_gemm2() {
    __shared__ __align__(16) float ws[64*64];
    __shared__ float sc[64], sh[64];
    int t = threadIdx.x;
    for (int i = t; i < 64*64; i += 128) ws[i] = g_wt1[i];
    if (t < 64) { sc[t] = g_scale[0][t]; sh[t] = g_shift[0][t]; }
    __syncthreads();

    size_t r = (size_t)blockIdx.x * 128 + t;
    const float4* yr = (const float4*)(g_Y1 + r * 64);
    float acc[64];
#pragma unroll
    for (int o = 0; o < 64; o++) acc[o] = 0.f;

#pragma unroll 1
    for (int kc = 0; kc < 16; kc++) {
        float4 yv = yr[kc];
        int kb = kc * 4;
        float ys[4] = {yv.x, yv.y, yv.z, yv.w};
#pragma unroll
        for (int kk = 0; kk < 4; kk++) {
            float xk = fmaxf(fmaf(ys[kk], sc[kb+kk], sh[kb+kk]), 0.f);
            const float* wr = &ws[(kb+kk)*64];
#pragma unroll
            for (int o = 0; o < 64; o += 4) {
                float4 w = *(const float4*)(wr + o);
                acc[o]   = fmaf(xk, w.x, acc[o]);
                acc[o+1] = fmaf(xk, w.y, acc[o+1]);
                acc[o+2] = fmaf(xk, w.z, acc[o+2]);
                acc[o+3] = fmaf(xk, w.w, acc[o+3]);
            }
        }
    }
    float4* Y = (float4*)(g_Y2 + r * 64);
#pragma unroll
    for (int o = 0; o < 64; o += 4) {
        float4 v = {acc[o], acc[o+1], acc[o+2], acc[o+3]};
        Y[o >> 2] = v;
    }
}

// ------------------------- GEMM layer 3: BN+ReLU(Y2) @ W2, K=64 -> OC=128 ------------------
__global__ __launch_bounds__(256)
void k_gemm3() {
    __shared__ __align__(16) float ws[64*128];
    __shared__ float sc[64], sh[64];
    int t = threadIdx.x;
    for (int i = t; i < 64*128; i += 256) ws[i] = g_wt2[i];
    if (t < 64) { sc[t] = g_scale[1][t]; sh[t] = g_shift[1][t]; }
    __syncthreads();

    size_t r = (size_t)blockIdx.x * 128 + (t >> 1);
    int half = (t & 1) * 64;
    const float4* yr = (const float4*)(g_Y2 + r * 64);
    float acc[64];
#pragma unroll
    for (int o = 0; o < 64; o++) acc[o] = 0.f;

#pragma unroll 1
    for (int kc = 0; kc < 16; kc++) {
        float4 yv = yr[kc];
        int kb = kc * 4;
        float ys[4] = {yv.x, yv.y, yv.z, yv.w};
#pragma unroll
        for (int kk = 0; kk < 4; kk++) {
            float xk = fmaxf(fmaf(ys[kk], sc[kb+kk], sh[kb+kk]), 0.f);
            const float* wr = &ws[(kb+kk)*128 + half];
#pragma unroll
            for (int o = 0; o < 64; o += 4) {
                float4 w = *(const float4*)(wr + o);
                acc[o]   = fmaf(xk, w.x, acc[o]);
                acc[o+1] = fmaf(xk, w.y, acc[o+1]);
                acc[o+2] = fmaf(xk, w.z, acc[o+2]);
                acc[o+3] = fmaf(xk, w.w, acc[o+3]);
            }
        }
    }
    float4* Y = (float4*)(g_Y3 + r * 128 + half);
#pragma unroll
    for (int o = 0; o < 64; o += 4) {
        float4 v = {acc[o], acc[o+1], acc[o+2], acc[o+3]};
        Y[o >> 2] = v;
    }
}

// ------------------------- per-channel partial sums (deterministic) -----------------------
__global__ __launch_bounds__(256)
void k_sums(int sel) {
    const float* Y = (sel == 0) ? g_Y1 : (sel == 1 ? g_Y2 : g_Y3);
    int OC = (sel == 2) ? 128 : 64;
    int t  = threadIdx.x;
    int c  = t % OC;
    int rg = t / OC;
    int ng = 256 / OC;
    size_t base = (size_t)blockIdx.x * 4096;
    float s = 0.f, s2 = 0.f;
    for (int rr = rg; rr < 4096; rr += ng) {
        float v = Y[(base + rr) * OC + c];
        s += v;
        s2 = fmaf(v, v, s2);
    }
    __shared__ float ss[256], ss2[256];
    ss[t] = s; ss2[t] = s2;
    __syncthreads();
    if (t < OC) {
        float a = ss[t], a2 = ss2[t];
        for (int g = 1; g < ng; g++) { a += ss[t + g*OC]; a2 += ss2[t + g*OC]; }
        g_psum[(size_t)blockIdx.x * OC + t] = a;
        g_psq [(size_t)blockIdx.x * OC + t] = a2;
    }
}

// ------------------------- finalize BN stats (double, fixed order) ------------------------
__global__ void k_finalize(const float* __restrict__ gma, const float* __restrict__ beta,
                           int OC, int layer) {
    int c = threadIdx.x;
    if (c >= OC) return;
    double s = 0.0, s2 = 0.0;
    for (int i = 0; i < 128; i++) {
        s  += (double)g_psum[i*OC + c];
        s2 += (double)g_psq [i*OC + c];
    }
    double inv = 1.0 / (double)NROWS;
    double mean = s * inv;
    double var  = s2 * inv - mean * mean;
    float scale = (float)((double)gma[c] * rsqrt(var + 1e-5));
    float shift = (float)((double)beta[c] - mean * (double)scale);
    g_scale[layer][c] = scale;
    g_shift[layer][c] = shift;
}

// ------------------------- BN+ReLU(Y3) + max over samples + transpose ---------------------
__global__ __launch_bounds__(128)
void k_pool(float* __restrict__ out) {
    int q = blockIdx.x;          // b*1024 + m
    int b = q >> 10, m = q & 1023;
    int t = threadIdx.x;         // oc
    float sc = g_scale[2][t], sh = g_shift[2][t];
    const float* Y = g_Y3 + (size_t)q * 32 * 128;
    float mx = -CUDART_INF_F;
#pragma unroll 4
    for (int s = 0; s < 32; s++)
        mx = fmaxf(mx, fmaf(Y[s*128 + t], sc, sh));
    mx = fmaxf(mx, 0.f);
    out[49152 + ((size_t)b * 128 + t) * 1024 + m] = mx;
}

// ------------------------- launch --------------------------------------------------------
extern "C" void kernel_launch(void* const* d_in, const int* in_sizes, int n_in,
                              void* d_out, int out_size) {
    const float* xyz = (const float*)d_in[0];
    const float* pts = (const float*)d_in[1];
    const float* w0  = (const float*)d_in[2];
    const float* g0  = (const float*)d_in[4];
    const float* be0 = (const float*)d_in[5];
    const float* w1  = (const float*)d_in[6];
    const float* g1  = (const float*)d_in[8];
    const float* be1 = (const float*)d_in[9];
    const float* w2  = (const float*)d_in[10];
    const float* g2  = (const float*)d_in[12];
    const float* be2 = (const float*)d_in[13];
    float* out = (float*)d_out;

    k_init<<<64, 256>>>(w0, w1, w2);
    k_fps<<<B_, 1024>>>(xyz, out);
    k_knn<<<B_*NP_, 128>>>(xyz);

    k_gemm1<<<NROWS/128, 128>>>(xyz, pts);
    k_sums<<<128, 256>>>(0);
    k_finalize<<<1, 64>>>(g0, be0, 64, 0);

    k_gemm2<<<NROWS/128, 128>>>();
    k_sums<<<128, 256>>>(1);
    k_finalize<<<1, 64>>>(g1, be1, 64, 1);

    k_gemm3<<<NROWS/128, 256>>>();
    k_sums<<<128, 256>>>(2);
    k_finalize<<<1, 128>>>(g2, be2, 128, 2);

    k_pool<<<B_*NP_, 128>>>(out);
}

// round 7
// speedup vs baseline: 1.6011x; 1.6011x over previous
#include <cuda_runtime.h>
#include <math_constants.h>

#define B_   16
#define N_   4096
#define NP_  1024
#define NS_  32
#define NROWS 524288   // B_*NP_*NS_

// ------------------------- static device scratch (no allocation) -------------------------
__device__ __align__(16) float g_newxyz[B_*NP_*3];
__device__ int   g_knn[B_*NP_*NS_];
__device__ __align__(16) float g_Y1[33554432];   // 524288 x 64
__device__ __align__(16) float g_Y2[33554432];   // 524288 x 64
__device__ __align__(16) float g_Y3[67108864];   // 524288 x 128
__device__ float g_psum[4096*128];
__device__ float g_psq [4096*128];
__device__ float g_scale[3][128];
__device__ float g_shift[3][128];
__device__ __align__(16) float g_wt0[67*64];
__device__ __align__(16) float g_wt1[64*64];
__device__ __align__(16) float g_wt2[64*128];

// ------------------------- init: transpose weights to [K][OC] -------------------------
__global__ void k_init(const float* __restrict__ w0, const float* __restrict__ w1,
                       const float* __restrict__ w2) {
    int t = blockIdx.x * blockDim.x + threadIdx.x;
    int stride = gridDim.x * blockDim.x;
    for (int l = t; l < 64*67; l += stride) { int oc = l / 67, k = l - oc*67; g_wt0[k*64 + oc] = w0[l]; }
    for (int l = t; l < 64*64; l += stride) { int oc = l >> 6, k = l & 63;    g_wt1[k*64 + oc] = w1[l]; }
    for (int l = t; l < 128*64; l += stride){ int oc = l >> 6, k = l & 63;    g_wt2[k*128 + oc] = w2[l]; }
}

// ------------------------- FPS: one block per batch, REDUX argmax ----------------------
// distances are sums of squares -> nonnegative -> float bits are u32-monotonic.
__global__ __launch_bounds__(1024)
void k_fps(const float* __restrict__ xyz, float* __restrict__ out) {
    int b = blockIdx.x, t = threadIdx.x;
    const float* X = xyz + (size_t)b * N_ * 3;
    float px[4], py[4], pz[4], dd[4];
#pragma unroll
    for (int j = 0; j < 4; j++) {
        int n = t*4 + j;
        px[j] = X[n*3]; py[j] = X[n*3+1]; pz[j] = X[n*3+2];
        dd[j] = 1e10f;
    }
    __shared__ float scx, scy, scz;
    __shared__ unsigned swv[32]; __shared__ int swi[32];
    if (t == 0) { scx = X[0]; scy = X[1]; scz = X[2]; }
    __syncthreads();
    float* nx = g_newxyz + (size_t)b * NP_ * 3;
    float* ox = out + (size_t)b * NP_ * 3;

    for (int i = 0; i < NP_; i++) {
        float ccx = scx, ccy = scy, ccz = scz;
        if (t == 0) {
            nx[i*3] = ccx; nx[i*3+1] = ccy; nx[i*3+2] = ccz;
            ox[i*3] = ccx; ox[i*3+1] = ccy; ox[i*3+2] = ccz;
        }
        float bv = -1.0f; int bi = 0;
#pragma unroll
        for (int j = 0; j < 4; j++) {
            float dx = __fsub_rn(px[j], ccx);
            float dy = __fsub_rn(py[j], ccy);
            float dz = __fsub_rn(pz[j], ccz);
            float d  = __fadd_rn(__fadd_rn(__fmul_rn(dx,dx), __fmul_rn(dy,dy)), __fmul_rn(dz,dz));
            dd[j] = fminf(dd[j], d);
            if (dd[j] > bv) { bv = dd[j]; bi = t*4 + j; }   // strict > keeps lowest idx on tie
        }
        unsigned kv   = __float_as_uint(bv);
        unsigned vmax = __reduce_max_sync(0xffffffffu, kv);
        unsigned cand = (kv == vmax) ? (unsigned)bi : 0xffffffffu;
        unsigned imin = __reduce_min_sync(0xffffffffu, cand);
        if ((t & 31) == 0) { swv[t>>5] = vmax; swi[t>>5] = (int)imin; }
        __syncthreads();
        if (t < 32) {
            unsigned kv2  = swv[t];
            int      ii   = swi[t];
            unsigned vm2  = __reduce_max_sync(0xffffffffu, kv2);
            unsigned c2   = (kv2 == vm2) ? (unsigned)ii : 0xffffffffu;
            unsigned win  = __reduce_min_sync(0xffffffffu, c2);
            if (t == 0) {
                const float* P = X + (size_t)win * 3;
                scx = P[0]; scy = P[1]; scz = P[2];
            }
        }
        __syncthreads();
    }
}

// monotonic u32 key for possibly-negative floats (min-order preserved)
__device__ __forceinline__ unsigned fkey(float v) {
    unsigned u = __float_as_uint(v);
    return u ^ (unsigned)(((int)u >> 31) | 0x80000000);
}

// ------------------------- kNN: block per query, REDUX extraction ----------------------
__global__ __launch_bounds__(128)
void k_knn(const float* __restrict__ xyz) {
    int q = blockIdx.x;              // b*1024 + m
    int b = q >> 10;
    int t = threadIdx.x;
    const float* X = xyz + (size_t)b * N_ * 3;
    const float* Q = g_newxyz + (size_t)q * 3;
    float qx = Q[0], qy = Q[1], qz = Q[2];
    float sqn = __fadd_rn(__fadd_rn(__fmul_rn(qx,qx), __fmul_rn(qy,qy)), __fmul_rn(qz,qz));

    __shared__ float sd[N_];
    float bv = CUDART_INF_F; int bi = 0x7fffffff;
#pragma unroll 4
    for (int i = 0; i < 32; i++) {
        int n = i*128 + t;
        float x = X[n*3], y = X[n*3+1], z = X[n*3+2];
        float sq  = __fadd_rn(__fadd_rn(__fmul_rn(x,x), __fmul_rn(y,y)), __fmul_rn(z,z));
        float dot = __fadd_rn(__fadd_rn(__fmul_rn(qx,x), __fmul_rn(qy,y)), __fmul_rn(qz,z));
        float d2  = __fsub_rn(__fadd_rn(sqn, sq), __fmul_rn(2.0f, dot));
        sd[n] = d2;
        if (d2 < bv || (d2 == bv && n < bi)) { bv = d2; bi = n; }
    }
    __shared__ unsigned sk[4]; __shared__ int si[4];
    int* KO = g_knn + (size_t)q * NS_;
    int w = t >> 5;

    for (int r = 0; r < NS_; r++) {
        unsigned key = fkey(bv);
        unsigned km  = __reduce_min_sync(0xffffffffu, key);
        unsigned cnd = (key == km) ? (unsigned)bi : 0xffffffffu;
        unsigned im  = __reduce_min_sync(0xffffffffu, cnd);
        if ((t & 31) == 0) { sk[w] = km; si[w] = (int)im; }
        __syncthreads();
        unsigned bk = sk[0]; int bix = si[0];
#pragma unroll
        for (int ww = 1; ww < 4; ww++) {
            unsigned kk = sk[ww]; int ii = si[ww];
            if (kk < bk || (kk == bk && ii < bix)) { bk = kk; bix = ii; }
        }
        if (t == 0) KO[r] = bix;
        if ((bix & 127) == t && r < NS_-1) {   // owner rescans its private column
            sd[bix] = CUDART_INF_F;
            bv = CUDART_INF_F; bi = 0x7fffffff;
            for (int i = 0; i < 32; i++) {
                int n = i*128 + t; float d = sd[n];
                if (d < bv || (d == bv && n < bi)) { bv = d; bi = n; }
            }
        }
        __syncthreads();
    }
}

// deterministic per-channel block partial sums (row-per-thread layers, 128 thr, 4 warps)
__device__ __forceinline__ void epilogue_sums_64(const float* acc, int t, int bid) {
    __shared__ float eps[4][64], epq[4][64];
    int w = t >> 5, lane = t & 31;
#pragma unroll 1
    for (int o = 0; o < 64; o++) {
        float s = acc[o];
        float q = acc[o]*acc[o];
#pragma unroll
        for (int off = 16; off; off >>= 1) {
            s += __shfl_down_sync(0xffffffffu, s, off);
            q += __shfl_down_sync(0xffffffffu, q, off);
        }
        if (lane == 0) { eps[w][o] = s; epq[w][o] = q; }
    }
    __syncthreads();
    if (t < 64) {
        float a  = eps[0][t] + eps[1][t] + eps[2][t] + eps[3][t];
        float a2 = epq[0][t] + epq[1][t] + epq[2][t] + epq[3][t];
        g_psum[(size_t)bid * 64 + t] = a;
        g_psq [(size_t)bid * 64 + t] = a2;
    }
}

// ------------------------- GEMM layer 1: fused gather, K=67 -> OC=64 ----------------------
__global__ __launch_bounds__(128)
void k_gemm1(const float* __restrict__ xyz, const float* __restrict__ pts) {
    __shared__ __align__(16) float ws[67*64];
    int t = threadIdx.x;
    for (int i = t; i < 67*64; i += 128) ws[i] = g_wt0[i];
    __syncthreads();

    size_t r = (size_t)blockIdx.x * 128 + t;
    int b  = (int)(r >> 15);
    int bm = (int)(r >> 5);
    int j  = g_knn[r];
    const float* P = xyz + ((size_t)b * N_ + j) * 3;
    const float* Q = g_newxyz + (size_t)bm * 3;
    float f0 = P[0] - Q[0], f1 = P[1] - Q[1], f2 = P[2] - Q[2];

    float acc[64];
#pragma unroll
    for (int o = 0; o < 64; o++) acc[o] = 0.f;

    float f3[3] = {f0, f1, f2};
#pragma unroll
    for (int k = 0; k < 3; k++) {
        float xk = f3[k];
        const float* wr = &ws[k*64];
#pragma unroll
        for (int o = 0; o < 64; o += 4) {
            float4 wv = *(const float4*)(wr + o);
            acc[o]   = fmaf(xk, wv.x, acc[o]);
            acc[o+1] = fmaf(xk, wv.y, acc[o+1]);
            acc[o+2] = fmaf(xk, wv.z, acc[o+2]);
            acc[o+3] = fmaf(xk, wv.w, acc[o+3]);
        }
    }
    const float4* prow = (const float4*)(pts + ((size_t)b * N_ + j) * 64);
    float4 nxt = __ldg(&prow[0]);
#pragma unroll 1
    for (int kc = 0; kc < 16; kc++) {
        float4 xv = nxt;
        nxt = __ldg(&prow[(kc < 15) ? (kc + 1) : 15]);
        const float* wr = &ws[(3 + kc*4) * 64];
        float xs[4] = {xv.x, xv.y, xv.z, xv.w};
#pragma unroll
        for (int kk = 0; kk < 4; kk++) {
            float xk = xs[kk];
#pragma unroll
            for (int o = 0; o < 64; o += 4) {
                float4 wv = *(const float4*)(wr + kk*64 + o);
                acc[o]   = fmaf(xk, wv.x, acc[o]);
                acc[o+1] = fmaf(xk, wv.y, acc[o+1]);
                acc[o+2] = fmaf(xk, wv.z, acc[o+2]);
                acc[o+3] = fmaf(xk, wv.w, acc[o+3]);
            }
        }
    }
    float4* Y = (float4*)(g_Y1 + r * 64);
#pragma unroll
    for (int o = 0; o < 64; o += 4) {
        float4 v = {acc[o], acc[o+1], acc[o+2], acc[o+3]};
        Y[o >> 2] = v;
    }
    __syncthreads();
    epilogue_sums_64(acc, t, blockIdx.x);
}

// ------------------------- GEMM layer 2: BN+ReLU(Y1) @ W1, K=64 -> OC=64 -------------------
__global__ __launch_bounds__(128)
void k_gemm2() {
    __shared__ __align__(16) float ws[64*64];
    __shared__ float sc[64], sh[64];
    int t = threadIdx.x;
    for (int i = t; i < 64*64; i += 128) ws[i] = g_wt1[i];
    if (t < 64) { sc[t] = g_scale[0][t]; sh[t] = g_shift[0][t]; }
    __syncthreads();

    size_t r = (size_t)blockIdx.x * 128 + t;
    const float4* yr = (const float4*)(g_Y1 + r * 64);
    float acc[64];
#pragma unroll
    for (int o = 0; o < 64; o++) acc[o] = 0.f;

    float4 nxt = yr[0];
#pragma unroll 1
    for (int kc = 0; kc < 16; kc++) {
        float4 yv = nxt;
        nxt = yr[(kc < 15) ? (kc + 1) : 15];
        int kb = kc * 4;
        float ys[4] = {yv.x, yv.y, yv.z, yv.w};
#pragma unroll
        for (int kk = 0; kk < 4; kk++) {
            float xk = fmaxf(fmaf(ys[kk], sc[kb+kk], sh[kb+kk]), 0.f);
            const float* wr = &ws[(kb+kk)*64];
#pragma unroll
            for (int o = 0; o < 64; o += 4) {
                float4 wv = *(const float4*)(wr + o);
                acc[o]   = fmaf(xk, wv.x, acc[o]);
                acc[o+1] = fmaf(xk, wv.y, acc[o+1]);
                acc[o+2] = fmaf(xk, wv.z, acc[o+2]);
                acc[o+3] = fmaf(xk, wv.w, acc[o+3]);
            }
        }
    }
    float4* Y = (float4*)(g_Y2 + r * 64);
#pragma unroll
    for (int o = 0; o < 64; o += 4) {
        float4 v = {acc[o], acc[o+1], acc[o+2], acc[o+3]};
        Y[o >> 2] = v;
    }
    __syncthreads();
    epilogue_sums_64(acc, t, blockIdx.x);
}

// ------------------------- GEMM layer 3: BN+ReLU(Y2) @ W2, K=64 -> OC=128 ------------------
__global__ __launch_bounds__(256)
void k_gemm3() {
    __shared__ __align__(16) float ws[64*128];
    __shared__ float sc[64], sh[64];
    __shared__ float eps[16][64], epq[16][64];
    int t = threadIdx.x;
    for (int i = t; i < 64*128; i += 256) ws[i] = g_wt2[i];
    if (t < 64) { sc[t] = g_scale[1][t]; sh[t] = g_shift[1][t]; }
    __syncthreads();

    size_t r = (size_t)blockIdx.x * 128 + (t >> 1);
    int half = (t & 1) * 64;
    const float4* yr = (const float4*)(g_Y2 + r * 64);
    float acc[64];
#pragma unroll
    for (int o = 0; o < 64; o++) acc[o] = 0.f;

    float4 nxt = yr[0];
#pragma unroll 1
    for (int kc = 0; kc < 16; kc++) {
        float4 yv = nxt;
        nxt = yr[(kc < 15) ? (kc + 1) : 15];
        int kb = kc * 4;
        float ys[4] = {yv.x, yv.y, yv.z, yv.w};
#pragma unroll
        for (int kk = 0; kk < 4; kk++) {
            float xk = fmaxf(fmaf(ys[kk], sc[kb+kk], sh[kb+kk]), 0.f);
            const float* wr = &ws[(kb+kk)*128 + half];
#pragma unroll
            for (int o = 0; o < 64; o += 4) {
                float4 wv = *(const float4*)(wr + o);
                acc[o]   = fmaf(xk, wv.x, acc[o]);
                acc[o+1] = fmaf(xk, wv.y, acc[o+1]);
                acc[o+2] = fmaf(xk, wv.z, acc[o+2]);
                acc[o+3] = fmaf(xk, wv.w, acc[o+3]);
            }
        }
    }
    float4* Y = (float4*)(g_Y3 + r * 128 + half);
#pragma unroll
    for (int o = 0; o < 64; o += 4) {
        float4 v = {acc[o], acc[o+1], acc[o+2], acc[o+3]};
        Y[o >> 2] = v;
    }

    // per-channel partial sums: lanes split by parity (lane&1 == half index)
    __syncthreads();
    int w = t >> 5, lane = t & 31;
#pragma unroll 1
    for (int o = 0; o < 64; o++) {
        float s = acc[o];
        float q = acc[o]*acc[o];
#pragma unroll
        for (int off = 2; off <= 16; off <<= 1) {
            s += __shfl_xor_sync(0xffffffffu, s, off);
            q += __shfl_xor_sync(0xffffffffu, q, off);
        }
        if (lane < 2) { eps[w*2 + lane][o] = s; epq[w*2 + lane][o] = q; }
    }
    __syncthreads();
    if (t < 128) {
        int hf = t >> 6, o = t & 63;
        float a = 0.f, a2 = 0.f;
#pragma unroll
        for (int wb = 0; wb < 8; wb++) { a += eps[wb*2 + hf][o]; a2 += epq[wb*2 + hf][o]; }
        g_psum[(size_t)blockIdx.x * 128 + t] = a;
        g_psq [(size_t)blockIdx.x * 128 + t] = a2;
    }
}

// ------------------------- finalize BN stats: one block per channel -----------------------
__global__ __launch_bounds__(256)
void k_fin(const float* __restrict__ gma, const float* __restrict__ beta,
           int OC, int layer) {
    int c = blockIdx.x, t = threadIdx.x;
    float s = 0.f, s2 = 0.f;
    for (int i = t; i < 4096; i += 256) {
        s  += g_psum[(size_t)i * OC + c];
        s2 += g_psq [(size_t)i * OC + c];
    }
#pragma unroll
    for (int off = 16; off; off >>= 1) {
        s  += __shfl_down_sync(0xffffffffu, s, off);
        s2 += __shfl_down_sync(0xffffffffu, s2, off);
    }
    __shared__ float a[8], a2[8];
    if ((t & 31) == 0) { a[t>>5] = s; a2[t>>5] = s2; }
    __syncthreads();
    if (t == 0) {
        double S = 0.0, S2 = 0.0;
#pragma unroll
        for (int wb = 0; wb < 8; wb++) { S += (double)a[wb]; S2 += (double)a2[wb]; }
        double inv  = 1.0 / (double)NROWS;
        double mean = S * inv;
        double var  = S2 * inv - mean * mean;
        float scale = (float)((double)gma[c] * rsqrt(var + 1e-5));
        float shift = (float)((double)beta[c] - mean * (double)scale);
        g_scale[layer][c] = scale;
        g_shift[layer][c] = shift;
    }
}

// ------------------------- BN+ReLU(Y3) + max pool + coalesced transpose -------------------
__global__ __launch_bounds__(128)
void k_pool(float* __restrict__ out) {
    __shared__ float sm[128][33];
    int t = threadIdx.x;
    int qbase = blockIdx.x * 32;           // 32 queries per block, same batch
    int b = qbase >> 10;
    float sc = g_scale[2][t], sh = g_shift[2][t];
#pragma unroll 1
    for (int qi = 0; qi < 32; qi++) {
        const float* Y = g_Y3 + (size_t)(qbase + qi) * 4096;
        float mx = -CUDART_INF_F;
#pragma unroll
        for (int s = 0; s < 32; s++)
            mx = fmaxf(mx, fmaf(Y[s*128 + t], sc, sh));
        sm[t][qi] = fmaxf(mx, 0.f);
    }
    __syncthreads();
    int mloc = t & 31, og = t >> 5;
    int mg = qbase & 1023;
#pragma unroll
    for (int i = 0; i < 32; i++) {
        int oc = og + i*4;
        out[49152 + ((size_t)(b * 128 + oc)) * 1024 + mg + mloc] = sm[oc][mloc];
    }
}

// ------------------------- launch --------------------------------------------------------
extern "C" void kernel_launch(void* const* d_in, const int* in_sizes, int n_in,
                              void* d_out, int out_size) {
    const float* xyz = (const float*)d_in[0];
    const float* pts = (const float*)d_in[1];
    const float* w0  = (const float*)d_in[2];
    const float* g0  = (const float*)d_in[4];
    const float* be0 = (const float*)d_in[5];
    const float* w1  = (const float*)d_in[6];
    const float* g1  = (const float*)d_in[8];
    const float* be1 = (const float*)d_in[9];
    const float* w2  = (const float*)d_in[10];
    const float* g2  = (const float*)d_in[12];
    const float* be2 = (const float*)d_in[13];
    float* out = (float*)d_out;

    k_init<<<64, 256>>>(w0, w1, w2);
    k_fps<<<B_, 1024>>>(xyz, out);
    k_knn<<<B_*NP_, 128>>>(xyz);

    k_gemm1<<<NROWS/128, 128>>>(xyz, pts);
    k_fin<<<64, 256>>>(g0, be0, 64, 0);

    k_gemm2<<<NROWS/128, 128>>>();
    k_fin<<<64, 256>>>(g1, be1, 64, 1);

    k_gemm3<<<NROWS/128, 256>>>();
    k_fin<<<128, 256>>>(g2, be2, 128, 2);

    k_pool<<<B_*NP_/32, 128>>>(out);
}

// round 8
// speedup vs baseline: 2.6797x; 1.6737x over previous
#include <cuda_runtime.h>
#include <math_constants.h>

#define B_   16
#define N_   4096
#define NP_  1024
#define NS_  32
#define NROWS 524288   // B_*NP_*NS_

// ------------------------- static device scratch (no allocation) -------------------------
__device__ __align__(16) float g_newxyz[B_*NP_*3];
__device__ int   g_knn[B_*NP_*NS_];
__device__ __align__(16) float g_P [4194304];    // 65536 x 64   pts @ W0[3:]
__device__ __align__(16) float g_Y1[33554432];   // blocked 4096 x 16 x 128 x 4
__device__ __align__(16) float g_Y2[33554432];   // blocked 4096 x 16 x 128 x 4
__device__ __align__(16) float g_Y3[67108864];   // blocked 4096 x 32 x 128 x 4
__device__ float g_psum[4096*128];
__device__ float g_psq [4096*128];
__device__ float g_scale[3][128];
__device__ float g_shift[3][128];
__device__ __align__(16) float g_wt0[67*64];
__device__ __align__(16) float g_wt1[64*64];
__device__ __align__(16) float g_wt2[64*128];

// ------------------------- init: transpose weights to [K][OC] -------------------------
__global__ void k_init(const float* __restrict__ w0, const float* __restrict__ w1,
                       const float* __restrict__ w2) {
    int t = blockIdx.x * blockDim.x + threadIdx.x;
    int stride = gridDim.x * blockDim.x;
    for (int l = t; l < 64*67; l += stride) { int oc = l / 67, k = l - oc*67; g_wt0[k*64 + oc] = w0[l]; }
    for (int l = t; l < 64*64; l += stride) { int oc = l >> 6, k = l & 63;    g_wt1[k*64 + oc] = w1[l]; }
    for (int l = t; l < 128*64; l += stride){ int oc = l >> 6, k = l & 63;    g_wt2[k*128 + oc] = w2[l]; }
}

// ------------------------- FPS: one block per batch, REDUX argmax ----------------------
__global__ __launch_bounds__(1024)
void k_fps(const float* __restrict__ xyz, float* __restrict__ out) {
    int b = blockIdx.x, t = threadIdx.x;
    const float* X = xyz + (size_t)b * N_ * 3;
    float px[4], py[4], pz[4], dd[4];
#pragma unroll
    for (int j = 0; j < 4; j++) {
        int n = t*4 + j;
        px[j] = X[n*3]; py[j] = X[n*3+1]; pz[j] = X[n*3+2];
        dd[j] = 1e10f;
    }
    __shared__ float scx, scy, scz;
    __shared__ unsigned swv[32]; __shared__ int swi[32];
    if (t == 0) { scx = X[0]; scy = X[1]; scz = X[2]; }
    __syncthreads();
    float* nx = g_newxyz + (size_t)b * NP_ * 3;
    float* ox = out + (size_t)b * NP_ * 3;

    for (int i = 0; i < NP_; i++) {
        float ccx = scx, ccy = scy, ccz = scz;
        if (t == 0) {
            nx[i*3] = ccx; nx[i*3+1] = ccy; nx[i*3+2] = ccz;
            ox[i*3] = ccx; ox[i*3+1] = ccy; ox[i*3+2] = ccz;
        }
        float bv = -1.0f; int bi = 0;
#pragma unroll
        for (int j = 0; j < 4; j++) {
            float dx = __fsub_rn(px[j], ccx);
            float dy = __fsub_rn(py[j], ccy);
            float dz = __fsub_rn(pz[j], ccz);
            float d  = __fadd_rn(__fadd_rn(__fmul_rn(dx,dx), __fmul_rn(dy,dy)), __fmul_rn(dz,dz));
            dd[j] = fminf(dd[j], d);
            if (dd[j] > bv) { bv = dd[j]; bi = t*4 + j; }
        }
        unsigned kv   = __float_as_uint(bv);
        unsigned vmax = __reduce_max_sync(0xffffffffu, kv);
        unsigned cand = (kv == vmax) ? (unsigned)bi : 0xffffffffu;
        unsigned imin = __reduce_min_sync(0xffffffffu, cand);
        if ((t & 31) == 0) { swv[t>>5] = vmax; swi[t>>5] = (int)imin; }
        __syncthreads();
        if (t < 32) {
            unsigned kv2  = swv[t];
            int      ii   = swi[t];
            unsigned vm2  = __reduce_max_sync(0xffffffffu, kv2);
            unsigned c2   = (kv2 == vm2) ? (unsigned)ii : 0xffffffffu;
            unsigned win  = __reduce_min_sync(0xffffffffu, c2);
            if (t == 0) {
                const float* Pp = X + (size_t)win * 3;
                scx = Pp[0]; scy = Pp[1]; scz = Pp[2];
            }
        }
        __syncthreads();
    }
}

__device__ __forceinline__ unsigned fkey(float v) {
    unsigned u = __float_as_uint(v);
    return u ^ (unsigned)(((int)u >> 31) | 0x80000000);
}

// ------------------------- kNN: block per query, REDUX extraction ----------------------
__global__ __launch_bounds__(128)
void k_knn(const float* __restrict__ xyz) {
    int q = blockIdx.x;
    int b = q >> 10;
    int t = threadIdx.x;
    const float* X = xyz + (size_t)b * N_ * 3;
    const float* Q = g_newxyz + (size_t)q * 3;
    float qx = Q[0], qy = Q[1], qz = Q[2];
    float sqn = __fadd_rn(__fadd_rn(__fmul_rn(qx,qx), __fmul_rn(qy,qy)), __fmul_rn(qz,qz));

    __shared__ float sd[N_];
    float bv = CUDART_INF_F; int bi = 0x7fffffff;
#pragma unroll 4
    for (int i = 0; i < 32; i++) {
        int n = i*128 + t;
        float x = X[n*3], y = X[n*3+1], z = X[n*3+2];
        float sq  = __fadd_rn(__fadd_rn(__fmul_rn(x,x), __fmul_rn(y,y)), __fmul_rn(z,z));
        float dot = __fadd_rn(__fadd_rn(__fmul_rn(qx,x), __fmul_rn(qy,y)), __fmul_rn(qz,z));
        float d2  = __fsub_rn(__fadd_rn(sqn, sq), __fmul_rn(2.0f, dot));
        sd[n] = d2;
        if (d2 < bv || (d2 == bv && n < bi)) { bv = d2; bi = n; }
    }
    __shared__ unsigned sk[4]; __shared__ int si[4];
    int* KO = g_knn + (size_t)q * NS_;
    int w = t >> 5;

    for (int r = 0; r < NS_; r++) {
        unsigned key = fkey(bv);
        unsigned km  = __reduce_min_sync(0xffffffffu, key);
        unsigned cnd = (key == km) ? (unsigned)bi : 0xffffffffu;
        unsigned im  = __reduce_min_sync(0xffffffffu, cnd);
        if ((t & 31) == 0) { sk[w] = km; si[w] = (int)im; }
        __syncthreads();
        unsigned bk = sk[0]; int bix = si[0];
#pragma unroll
        for (int ww = 1; ww < 4; ww++) {
            unsigned kk = sk[ww]; int ii = si[ww];
            if (kk < bk || (kk == bk && ii < bix)) { bk = kk; bix = ii; }
        }
        if (t == 0) KO[r] = bix;
        if ((bix & 127) == t && r < NS_-1) {
            sd[bix] = CUDART_INF_F;
            bv = CUDART_INF_F; bi = 0x7fffffff;
            for (int i = 0; i < 32; i++) {
                int n = i*128 + t; float d = sd[n];
                if (d < bv || (d == bv && n < bi)) { bv = d; bi = n; }
            }
        }
        __syncthreads();
    }
}

// ------------------------- P = pts @ W0[3:,:]  (dense, 65536 rows) ------------------------
__global__ __launch_bounds__(128)
void k_pre(const float* __restrict__ pts) {
    __shared__ __align__(16) float ws[64*64];
    int t = threadIdx.x;
    for (int i = t; i < 64*64; i += 128) ws[i] = g_wt0[192 + i];
    __syncthreads();

    size_t rr = (size_t)blockIdx.x * 128 + t;
    const float4* xr = (const float4*)(pts + rr * 64);
    float acc[64];
#pragma unroll
    for (int o = 0; o < 64; o++) acc[o] = 0.f;

    float4 a0 = __ldg(&xr[0]);
    float4 a1 = __ldg(&xr[1]);
#pragma unroll 1
    for (int kc = 0; kc < 16; kc++) {
        float4 xv = a0; a0 = a1;
        a1 = __ldg(&xr[(kc < 14) ? (kc + 2) : 15]);
        int kb = kc * 4;
        float xs[4] = {xv.x, xv.y, xv.z, xv.w};
#pragma unroll
        for (int kk = 0; kk < 4; kk++) {
            float xk = xs[kk];
            const float* wr = &ws[(kb+kk)*64];
#pragma unroll
            for (int o = 0; o < 64; o += 4) {
                float4 wv = *(const float4*)(wr + o);
                acc[o]   = fmaf(xk, wv.x, acc[o]);
                acc[o+1] = fmaf(xk, wv.y, acc[o+1]);
                acc[o+2] = fmaf(xk, wv.z, acc[o+2]);
                acc[o+3] = fmaf(xk, wv.w, acc[o+3]);
            }
        }
    }
    float4* po = (float4*)(g_P + rr * 64);
#pragma unroll
    for (int o = 0; o < 64; o += 4) {
        float4 v = {acc[o], acc[o+1], acc[o+2], acc[o+3]};
        po[o >> 2] = v;
    }
}

// smem-tile based per-block channel sums for 64-ch layers (128 threads)
__device__ __forceinline__ void tile_sums_64(float* tile, float* ps, float* pq,
                                             const float* acc, int t, int bid) {
    // write own row (stride 65, conflict-free)
#pragma unroll
    for (int o = 0; o < 64; o++) tile[t*65 + o] = acc[o];
    __syncthreads();
    int c = t & 63, g = t >> 6;
    float s = 0.f, q = 0.f;
#pragma unroll 4
    for (int r = g*64; r < g*64 + 64; r++) {
        float v = tile[r*65 + c];
        s += v; q = fmaf(v, v, q);
    }
    ps[g*64 + c] = s; pq[g*64 + c] = q;
    __syncthreads();
    if (t < 64) {
        g_psum[(size_t)bid*64 + t] = ps[t] + ps[64 + t];
        g_psq [(size_t)bid*64 + t] = pq[t] + pq[64 + t];
    }
}

// ------------------------- layer 1: gather(P) + rel_xyz @ W0[:3]  -------------------------
__global__ __launch_bounds__(128)
void k_gemm1(const float* __restrict__ xyz) {
    __shared__ float ws[192];
    __shared__ float tile[128*65];
    __shared__ float ps[128], pq[128];
    int t = threadIdx.x;
    for (int i = t; i < 192; i += 128) ws[i] = g_wt0[i];
    __syncthreads();

    size_t r = (size_t)blockIdx.x * 128 + t;
    int b  = (int)(r >> 15);
    int bm = (int)(r >> 5);
    int j  = g_knn[r];
    const float* Pt = xyz + ((size_t)b * N_ + j) * 3;
    const float* Q  = g_newxyz + (size_t)bm * 3;
    float f0 = Pt[0] - Q[0], f1 = Pt[1] - Q[1], f2 = Pt[2] - Q[2];

    const float4* prow = (const float4*)(g_P + ((size_t)b * N_ + j) * 64);
    float acc[64];
    float4 a0 = __ldg(&prow[0]);
    float4 a1 = __ldg(&prow[1]);
    float4* yo = (float4*)g_Y1 + (size_t)blockIdx.x * 2048 + t;
#pragma unroll 1
    for (int kc = 0; kc < 16; kc++) {
        float4 pv = a0; a0 = a1;
        a1 = __ldg(&prow[(kc < 14) ? (kc + 2) : 15]);
        int o = kc * 4;
        float ss[4] = {pv.x, pv.y, pv.z, pv.w};
#pragma unroll
        for (int kk = 0; kk < 4; kk++) {
            float v = ss[kk];
            v = fmaf(f0, ws[o+kk],       v);
            v = fmaf(f1, ws[64 + o+kk],  v);
            v = fmaf(f2, ws[128 + o+kk], v);
            acc[o+kk] = v;
        }
        float4 st = {acc[o], acc[o+1], acc[o+2], acc[o+3]};
        yo[kc*128] = st;
    }
    __syncthreads();
    tile_sums_64(tile, ps, pq, acc, t, blockIdx.x);
}

// ------------------------- layer 2: BN0+ReLU(Y1) @ W1 (blocked, coalesced) ----------------
__global__ __launch_bounds__(128)
void k_gemm2() {
    extern __shared__ __align__(16) float dyn[];
    float* ws   = dyn;            // 4096
    float* sc   = ws + 4096;      // 64
    float* sh   = sc + 64;        // 64
    float* tile = sh + 64;        // 8320
    float* ps   = tile + 8320;    // 128
    float* pq   = ps + 128;       // 128
    int t = threadIdx.x;
    for (int i = t; i < 64*64; i += 128) ws[i] = g_wt1[i];
    if (t < 64) { sc[t] = g_scale[0][t]; sh[t] = g_shift[0][t]; }
    __syncthreads();

    const float4* xr = (const float4*)g_Y1 + (size_t)blockIdx.x * 2048 + t;
    float acc[64];
#pragma unroll
    for (int o = 0; o < 64; o++) acc[o] = 0.f;

    float4 a0 = xr[0];
    float4 a1 = xr[128];
#pragma unroll 1
    for (int kc = 0; kc < 16; kc++) {
        float4 yv = a0; a0 = a1;
        a1 = xr[((kc < 14) ? (kc + 2) : 15) * 128];
        int kb = kc * 4;
        float ys[4] = {yv.x, yv.y, yv.z, yv.w};
#pragma unroll
        for (int kk = 0; kk < 4; kk++) {
            float xk = fmaxf(fmaf(ys[kk], sc[kb+kk], sh[kb+kk]), 0.f);
            const float* wr = &ws[(kb+kk)*64];
#pragma unroll
            for (int o = 0; o < 64; o += 4) {
                float4 wv = *(const float4*)(wr + o);
                acc[o]   = fmaf(xk, wv.x, acc[o]);
                acc[o+1] = fmaf(xk, wv.y, acc[o+1]);
                acc[o+2] = fmaf(xk, wv.z, acc[o+2]);
                acc[o+3] = fmaf(xk, wv.w, acc[o+3]);
            }
        }
    }
    float4* yo = (float4*)g_Y2 + (size_t)blockIdx.x * 2048 + t;
#pragma unroll
    for (int kc = 0; kc < 16; kc++) {
        float4 v = {acc[kc*4], acc[kc*4+1], acc[kc*4+2], acc[kc*4+3]};
        yo[kc*128] = v;
    }
    __syncthreads();
    tile_sums_64(tile, ps, pq, acc, t, blockIdx.x);
}

// ------------------------- layer 3: BN1+ReLU(Y2) @ W2 -> 128 ch (blocked) -----------------
__global__ __launch_bounds__(256)
void k_gemm3() {
    extern __shared__ __align__(16) float dyn[];
    float* ws   = dyn;             // 8192
    float* sc   = ws + 8192;       // 64
    float* sh   = sc + 64;         // 64
    float* tile = sh + 64;         // 128*129 = 16512
    float* ps   = tile + 16512;    // 256
    float* pq   = ps + 256;        // 256
    int t = threadIdx.x;
    for (int i = t; i < 64*128; i += 256) ws[i] = g_wt2[i];
    if (t < 64) { sc[t] = g_scale[1][t]; sh[t] = g_shift[1][t]; }
    __syncthreads();

    int row  = t & 127;
    int half = t >> 7;
    const float4* xr = (const float4*)g_Y2 + (size_t)blockIdx.x * 2048 + row;
    float acc[64];
#pragma unroll
    for (int o = 0; o < 64; o++) acc[o] = 0.f;

    float4 a0 = xr[0];
    float4 a1 = xr[128];
#pragma unroll 1
    for (int kc = 0; kc < 16; kc++) {
        float4 yv = a0; a0 = a1;
        a1 = xr[((kc < 14) ? (kc + 2) : 15) * 128];
        int kb = kc * 4;
        float ys[4] = {yv.x, yv.y, yv.z, yv.w};
#pragma unroll
        for (int kk = 0; kk < 4; kk++) {
            float xk = fmaxf(fmaf(ys[kk], sc[kb+kk], sh[kb+kk]), 0.f);
            const float* wr = &ws[(kb+kk)*128 + half*64];
#pragma unroll
            for (int o = 0; o < 64; o += 4) {
                float4 wv = *(const float4*)(wr + o);
                acc[o]   = fmaf(xk, wv.x, acc[o]);
                acc[o+1] = fmaf(xk, wv.y, acc[o+1]);
                acc[o+2] = fmaf(xk, wv.z, acc[o+2]);
                acc[o+3] = fmaf(xk, wv.w, acc[o+3]);
            }
        }
    }
    float4* yo = (float4*)g_Y3 + (size_t)blockIdx.x * 4096 + (size_t)half * 2048 + row;
#pragma unroll
    for (int kc = 0; kc < 16; kc++) {
        float4 v = {acc[kc*4], acc[kc*4+1], acc[kc*4+2], acc[kc*4+3]};
        yo[kc*128] = v;
    }

    // tile sums: 128 channels, stride-129 pad (conflict-free)
#pragma unroll
    for (int o = 0; o < 64; o++) tile[row*129 + half*64 + o] = acc[o];
    __syncthreads();
    int c = t & 127, g = t >> 7;
    float s = 0.f, q = 0.f;
#pragma unroll 4
    for (int r = g*64; r < g*64 + 64; r++) {
        float v = tile[r*129 + c];
        s += v; q = fmaf(v, v, q);
    }
    ps[g*128 + c] = s; pq[g*128 + c] = q;
    __syncthreads();
    if (t < 128) {
        g_psum[(size_t)blockIdx.x*128 + t] = ps[t] + ps[128 + t];
        g_psq [(size_t)blockIdx.x*128 + t] = pq[t] + pq[128 + t];
    }
}

// ------------------------- finalize BN stats: one block per channel -----------------------
__global__ __launch_bounds__(256)
void k_fin(const float* __restrict__ gma, const float* __restrict__ beta,
           int OC, int layer) {
    int c = blockIdx.x, t = threadIdx.x;
    float s = 0.f, s2 = 0.f;
    for (int i = t; i < 4096; i += 256) {
        s  += g_psum[(size_t)i * OC + c];
        s2 += g_psq [(size_t)i * OC + c];
    }
#pragma unroll
    for (int off = 16; off; off >>= 1) {
        s  += __shfl_down_sync(0xffffffffu, s, off);
        s2 += __shfl_down_sync(0xffffffffu, s2, off);
    }
    __shared__ float a[8], a2[8];
    if ((t & 31) == 0) { a[t>>5] = s; a2[t>>5] = s2; }
    __syncthreads();
    if (t == 0) {
        double S = 0.0, S2 = 0.0;
#pragma unroll
        for (int wb = 0; wb < 8; wb++) { S += (double)a[wb]; S2 += (double)a2[wb]; }
        double inv  = 1.0 / (double)NROWS;
        double mean = S * inv;
        double var  = S2 * inv - mean * mean;
        float scale = (float)((double)gma[c] * rsqrt(var + 1e-5));
        float shift = (float)((double)beta[c] - mean * (double)scale);
        g_scale[layer][c] = scale;
        g_shift[layer][c] = shift;
    }
}

// ------------------------- BN2+ReLU(Y3) + max pool + transposed write ---------------------
__global__ __launch_bounds__(128)
void k_pool(float* __restrict__ out) {
    __shared__ float ssc[128], ssh[128];
    __shared__ float sm[4*128];
    int t = threadIdx.x;
    ssc[t] = g_scale[2][t]; ssh[t] = g_shift[2][t];
    __syncthreads();

    const float4* Y = (const float4*)g_Y3 + (size_t)blockIdx.x * 4096 + t;
    int w = t >> 5;
#pragma unroll 1
    for (int kc = 0; kc < 32; kc++) {
        float4 v = Y[kc*128];
        int ch = ((kc >> 4) << 6) + ((kc & 15) << 2);
        float m0 = fmaxf(fmaf(v.x, ssc[ch],   ssh[ch]),   0.f);
        float m1 = fmaxf(fmaf(v.y, ssc[ch+1], ssh[ch+1]), 0.f);
        float m2 = fmaxf(fmaf(v.z, ssc[ch+2], ssh[ch+2]), 0.f);
        float m3 = fmaxf(fmaf(v.w, ssc[ch+3], ssh[ch+3]), 0.f);
        // nonneg floats: bits are u32-monotonic
        unsigned r0 = __reduce_max_sync(0xffffffffu, __float_as_uint(m0));
        unsigned r1 = __reduce_max_sync(0xffffffffu, __float_as_uint(m1));
        unsigned r2 = __reduce_max_sync(0xffffffffu, __float_as_uint(m2));
        unsigned r3 = __reduce_max_sync(0xffffffffu, __float_as_uint(m3));
        if ((t & 31) == 0) {
            sm[w*128 + ch]   = __uint_as_float(r0);
            sm[w*128 + ch+1] = __uint_as_float(r1);
            sm[w*128 + ch+2] = __uint_as_float(r2);
            sm[w*128 + ch+3] = __uint_as_float(r3);
        }
    }
    __syncthreads();
    int q0 = blockIdx.x * 4;
    int b  = q0 >> 10;
#pragma unroll
    for (int qi = 0; qi < 4; qi++) {
        int m = (q0 + qi) & 1023;
        out[49152 + ((size_t)b * 128 + t) * 1024 + m] = sm[qi*128 + t];
    }
}

// ------------------------- launch --------------------------------------------------------
extern "C" void kernel_launch(void* const* d_in, const int* in_sizes, int n_in,
                              void* d_out, int out_size) {
    const float* xyz = (const float*)d_in[0];
    const float* pts = (const float*)d_in[1];
    const float* w0  = (const float*)d_in[2];
    const float* g0  = (const float*)d_in[4];
    const float* be0 = (const float*)d_in[5];
    const float* w1  = (const float*)d_in[6];
    const float* g1  = (const float*)d_in[8];
    const float* be1 = (const float*)d_in[9];
    const float* w2  = (const float*)d_in[10];
    const float* g2  = (const float*)d_in[12];
    const float* be2 = (const float*)d_in[13];
    float* out = (float*)d_out;

    const int SMEM2 = 12800 * 4;   // 51200 B
    const int SMEM3 = 25344 * 4;   // 101376 B
    cudaFuncSetAttribute(k_gemm2, cudaFuncAttributeMaxDynamicSharedMemorySize, SMEM2);
    cudaFuncSetAttribute(k_gemm3, cudaFuncAttributeMaxDynamicSharedMemorySize, SMEM3);

    k_init<<<64, 256>>>(w0, w1, w2);
    k_pre<<<512, 128>>>(pts);
    k_fps<<<B_, 1024>>>(xyz, out);
    k_knn<<<B_*NP_, 128>>>(xyz);

    k_gemm1<<<NROWS/128, 128>>>(xyz);
    k_fin<<<64, 256>>>(g0, be0, 64, 0);

    k_gemm2<<<NROWS/128, 128, SMEM2>>>();
    k_fin<<<64, 256>>>(g1, be1, 64, 1);

    k_gemm3<<<NROWS/128, 256, SMEM3>>>();
    k_fin<<<128, 256>>>(g2, be2, 128, 2);

    k_pool<<<NROWS/128, 128>>>(out);
}

// round 9
// speedup vs baseline: 3.4214x; 1.2768x over previous
#include <cuda_runtime.h>
#include <math_constants.h>

#define B_   16
#define N_   4096
#define NP_  1024
#define NS_  32
#define NROWS 524288   // B_*NP_*NS_

typedef unsigned long long ull;

// ------------------------- static device scratch (no allocation) -------------------------
__device__ __align__(16) float g_newxyz[B_*NP_*3];
__device__ __align__(16) float4 g_xyzw[B_*N_];       // (x,y,z,sq)
__device__ int   g_knn[B_*NP_*NS_];
__device__ __align__(16) float g_P [4194304];    // 65536 x 64   pts @ W0[3:]
__device__ __align__(16) float g_Y1[33554432];   // blocked 4096 x 16 x 128 x 4
__device__ __align__(16) float g_Y2[33554432];   // blocked 4096 x 16 x 128 x 4
__device__ __align__(16) float g_Y3[67108864];   // blocked 4096 x 32 x 128 x 4
__device__ float g_psum[4096*128];
__device__ float g_psq [4096*128];
__device__ float g_scale[3][128];
__device__ float g_shift[3][128];
__device__ __align__(16) float g_wt0[67*64];
__device__ __align__(16) float g_wt1[64*64];
__device__ __align__(16) float g_wt2[64*128];

// ------------------------- f32x2 packed helpers -------------------------
__device__ __forceinline__ void fma2(ull& d, ull a, ull b) {
    asm("fma.rn.f32x2 %0, %1, %2, %0;" : "+l"(d) : "l"(a), "l"(b));
}
__device__ __forceinline__ ull pk2(float x) {
    ull u;
    asm("mov.b64 %0, {%1, %2};" : "=l"(u) : "f"(x), "f"(x));
    return u;
}
__device__ __forceinline__ float2 up2(ull u) {
    float2 f;
    asm("mov.b64 {%0, %1}, %2;" : "=f"(f.x), "=f"(f.y) : "l"(u));
    return f;
}

// ------------------------- init: transpose weights to [K][OC] -------------------------
__global__ void k_init(const float* __restrict__ w0, const float* __restrict__ w1,
                       const float* __restrict__ w2) {
    int t = blockIdx.x * blockDim.x + threadIdx.x;
    int stride = gridDim.x * blockDim.x;
    for (int l = t; l < 64*67; l += stride) { int oc = l / 67, k = l - oc*67; g_wt0[k*64 + oc] = w0[l]; }
    for (int l = t; l < 64*64; l += stride) { int oc = l >> 6, k = l & 63;    g_wt1[k*64 + oc] = w1[l]; }
    for (int l = t; l < 128*64; l += stride){ int oc = l >> 6, k = l & 63;    g_wt2[k*128 + oc] = w2[l]; }
}

// ------------------------- fused front: P precompute | xyzw table | FPS -------------------
// blocks [0,128): P = pts @ W0[3:]   (512 rows/block, half-row per thread)
// blocks [128,192): xyzw table
// blocks [192,208): FPS (one block per batch)
__global__ __launch_bounds__(1024)
void k_front(const float* __restrict__ xyz, const float* __restrict__ pts,
             float* __restrict__ out) {
    __shared__ __align__(16) float ws[4096];
    __shared__ float scx, scy, scz;
    __shared__ unsigned swv[32]; __shared__ int swi[32];
    int blk = blockIdx.x, t = threadIdx.x;

    if (blk < 128) {
        // ---- P = pts @ W0[3:,:]
        for (int i = t; i < 4096; i += 1024) ws[i] = g_wt0[192 + i];
        __syncthreads();
        int row  = blk * 512 + (t >> 1);
        int half = (t & 1) * 32;
        const float4* xr = (const float4*)(pts + (size_t)row * 64);
        ull acc2[16];
#pragma unroll
        for (int p = 0; p < 16; p++) acc2[p] = 0ull;
        float4 a0 = __ldg(&xr[0]);
        float4 a1 = __ldg(&xr[1]);
#pragma unroll 1
        for (int kc = 0; kc < 16; kc++) {
            float4 xv = a0; a0 = a1;
            a1 = __ldg(&xr[(kc < 14) ? (kc + 2) : 15]);
            float xs[4] = {xv.x, xv.y, xv.z, xv.w};
#pragma unroll
            for (int kk = 0; kk < 4; kk++) {
                ull xk2 = pk2(xs[kk]);
                const ulonglong2* wr = (const ulonglong2*)(ws + (kc*4 + kk)*64 + half);
#pragma unroll
                for (int p = 0; p < 8; p++) {
                    ulonglong2 wv = wr[p];
                    fma2(acc2[p*2],   xk2, wv.x);
                    fma2(acc2[p*2+1], xk2, wv.y);
                }
            }
        }
        ulonglong2* po = (ulonglong2*)(g_P + (size_t)row * 64 + half);
#pragma unroll
        for (int p = 0; p < 8; p++) po[p] = make_ulonglong2(acc2[2*p], acc2[2*p+1]);
        return;
    }
    if (blk < 192) {
        // ---- xyzw table (x,y,z,sq) with exact-chain sq
        int n = (blk - 128) * 1024 + t;
        const float* X = xyz + (size_t)n * 3;
        float x = X[0], y = X[1], z = X[2];
        float sq = __fadd_rn(__fadd_rn(__fmul_rn(x,x), __fmul_rn(y,y)), __fmul_rn(z,z));
        g_xyzw[n] = make_float4(x, y, z, sq);
        return;
    }

    // ---- FPS
    int b = blk - 192;
    const float* X = xyz + (size_t)b * N_ * 3;
    float px[4], py[4], pz[4], dd[4];
#pragma unroll
    for (int j = 0; j < 4; j++) {
        int n = t*4 + j;
        px[j] = X[n*3]; py[j] = X[n*3+1]; pz[j] = X[n*3+2];
        dd[j] = 1e10f;
    }
    if (t == 0) { scx = X[0]; scy = X[1]; scz = X[2]; }
    __syncthreads();
    float* nx = g_newxyz + (size_t)b * NP_ * 3;
    float* ox = out + (size_t)b * NP_ * 3;

    for (int i = 0; i < NP_; i++) {
        float ccx = scx, ccy = scy, ccz = scz;
        if (t == 0) {
            nx[i*3] = ccx; nx[i*3+1] = ccy; nx[i*3+2] = ccz;
            ox[i*3] = ccx; ox[i*3+1] = ccy; ox[i*3+2] = ccz;
        }
        float bv = -1.0f; int bi = 0;
#pragma unroll
        for (int j = 0; j < 4; j++) {
            float dx = __fsub_rn(px[j], ccx);
            float dy = __fsub_rn(py[j], ccy);
            float dz = __fsub_rn(pz[j], ccz);
            float d  = __fadd_rn(__fadd_rn(__fmul_rn(dx,dx), __fmul_rn(dy,dy)), __fmul_rn(dz,dz));
            dd[j] = fminf(dd[j], d);
            if (dd[j] > bv) { bv = dd[j]; bi = t*4 + j; }
        }
        unsigned kv   = __float_as_uint(bv);
        unsigned vmax = __reduce_max_sync(0xffffffffu, kv);
        unsigned cand = (kv == vmax) ? (unsigned)bi : 0xffffffffu;
        unsigned imin = __reduce_min_sync(0xffffffffu, cand);
        if ((t & 31) == 0) { swv[t>>5] = vmax; swi[t>>5] = (int)imin; }
        __syncthreads();
        if (t < 32) {
            unsigned kv2  = swv[t];
            int      ii   = swi[t];
            unsigned vm2  = __reduce_max_sync(0xffffffffu, kv2);
            unsigned c2   = (kv2 == vm2) ? (unsigned)ii : 0xffffffffu;
            unsigned win  = __reduce_min_sync(0xffffffffu, c2);
            if (t == 0) {
                const float* Pp = X + (size_t)win * 3;
                scx = Pp[0]; scy = Pp[1]; scz = Pp[2];
            }
        }
        __syncthreads();
    }
}

__device__ __forceinline__ unsigned fkey(float v) {
    unsigned u = __float_as_uint(v);
    return u ^ (unsigned)(((int)u >> 31) | 0x80000000);
}

// ------------------------- kNN: histogram radix-select (one block / query) -----------------
__global__ __launch_bounds__(128)
void k_knn() {
    int q = blockIdx.x, b = q >> 10, t = threadIdx.x;
    int lane = t & 31, w = t >> 5;
    const float4* X4 = g_xyzw + (size_t)b * N_;
    const float* Q = g_newxyz + (size_t)q * 3;
    float qx = Q[0], qy = Q[1], qz = Q[2];
    float sqn = __fadd_rn(__fadd_rn(__fmul_rn(qx,qx), __fmul_rn(qy,qy)), __fmul_rn(qz,qz));

    unsigned key[32];
#pragma unroll
    for (int i = 0; i < 32; i++) {
        float4 v = __ldg(&X4[i*128 + t]);
        float dot = __fadd_rn(__fadd_rn(__fmul_rn(qx,v.x), __fmul_rn(qy,v.y)), __fmul_rn(qz,v.z));
        float d2  = __fsub_rn(__fadd_rn(sqn, v.w), __fmul_rn(2.0f, dot));
        key[i] = fkey(d2);
    }

    __shared__ unsigned hist[2048];
    __shared__ unsigned sw[4];
    __shared__ unsigned spiv[3];
    __shared__ unsigned candk[64];
    __shared__ int candi[64];
    __shared__ int candn;

    // ---- level 1: 11-bit histogram
    for (int j = t; j < 2048; j += 128) hist[j] = 0;
    if (t == 0) candn = 0;
    __syncthreads();
#pragma unroll
    for (int i = 0; i < 32; i++) atomicAdd(&hist[key[i] >> 21], 1u);
    __syncthreads();
    unsigned s = 0;
#pragma unroll
    for (int j = 0; j < 16; j++) s += hist[t*16 + j];
    unsigned inc = s;
#pragma unroll
    for (int o = 1; o < 32; o <<= 1) { unsigned nn = __shfl_up_sync(~0u, inc, o); if (lane >= o) inc += nn; }
    if (lane == 31) sw[w] = inc;
    __syncthreads();
    unsigned wbase = 0;
    for (int j = 0; j < w; j++) wbase += sw[j];
    unsigned base = wbase + inc - s;
    if (base < 32 && base + s >= 32) {
        unsigned cum = base;
#pragma unroll
        for (int j = 0; j < 16; j++) {
            unsigned c = hist[t*16 + j];
            if (cum + c >= 32) { spiv[0] = t*16 + j; spiv[1] = cum; spiv[2] = c; break; }
            cum += c;
        }
    }
    __syncthreads();
    unsigned pb1 = spiv[0];
    unsigned cb  = spiv[1];
    unsigned pc  = spiv[2];
    unsigned Kstar, width;

    if (pc > 64) {
        // ---- level 2: next 11 bits within pivot bucket
        unsigned need2 = 32 - cb;
        for (int j = t; j < 2048; j += 128) hist[j] = 0;
        __syncthreads();
#pragma unroll
        for (int i = 0; i < 32; i++)
            if ((key[i] >> 21) == pb1) atomicAdd(&hist[(key[i] >> 10) & 2047], 1u);
        __syncthreads();
        s = 0;
#pragma unroll
        for (int j = 0; j < 16; j++) s += hist[t*16 + j];
        inc = s;
#pragma unroll
        for (int o = 1; o < 32; o <<= 1) { unsigned nn = __shfl_up_sync(~0u, inc, o); if (lane >= o) inc += nn; }
        if (lane == 31) sw[w] = inc;
        __syncthreads();
        wbase = 0;
        for (int j = 0; j < w; j++) wbase += sw[j];
        base = wbase + inc - s;
        if (base < need2 && base + s >= need2) {
            unsigned cum = base;
#pragma unroll
            for (int j = 0; j < 16; j++) {
                unsigned c = hist[t*16 + j];
                if (cum + c >= need2) { spiv[0] = t*16 + j; spiv[1] = cum; break; }
                cum += c;
            }
        }
        __syncthreads();
        Kstar = (pb1 << 21) | (spiv[0] << 10);
        width = 1u << 10;
        cb = cb + spiv[1];
        __syncthreads();
    } else {
        Kstar = pb1 << 21;
        width = 1u << 21;
    }

    // ---- emission: qualifiers (key < Kstar) deterministically by scan
    int ct = 0;
#pragma unroll
    for (int i = 0; i < 32; i++) ct += (key[i] < Kstar);
    int inci = ct;
#pragma unroll
    for (int o = 1; o < 32; o <<= 1) { int nn = __shfl_up_sync(~0u, inci, o); if (lane >= o) inci += nn; }
    if (lane == 31) sw[w] = (unsigned)inci;
    __syncthreads();
    int wb = 0;
    for (int j = 0; j < w; j++) wb += (int)sw[j];
    int slot = wb + inci - ct;
    int* KO = g_knn + (size_t)q * NS_;
#pragma unroll
    for (int i = 0; i < 32; i++) {
        unsigned k = key[i];
        if (k < Kstar) { KO[slot++] = i*128 + t; }
        else if (k - Kstar < width) {
            int p = atomicAdd(&candn, 1);
            if (p < 64) { candk[p] = k; candi[p] = i*128 + t; }
        }
    }
    __syncthreads();
    // ---- pivot-bucket candidates: exact rank by (key, index)
    int L = candn; if (L > 64) L = 64;
    int need = 32 - (int)cb;
    if (t < L) {
        unsigned mk = candk[t]; int mi = candi[t];
        int rank = 0;
        for (int j = 0; j < L; j++) {
            unsigned kj = candk[j];
            rank += (kj < mk) || (kj == mk && candi[j] < mi);
        }
        if (rank < need) KO[cb + rank] = mi;
    }
}

// ------------------------- layer 1: gather(P) + rel_xyz @ W0[:3]  -------------------------
__global__ __launch_bounds__(128)
void k_gemm1(const float* __restrict__ xyz) {
    __shared__ float ws[192];
    __shared__ float tile[128*65];
    __shared__ float ps[128], pq[128];
    int t = threadIdx.x;
    for (int i = t; i < 192; i += 128) ws[i] = g_wt0[i];
    __syncthreads();

    size_t r = (size_t)blockIdx.x * 128 + t;
    int b  = (int)(r >> 15);
    int bm = (int)(r >> 5);
    int j  = g_knn[r];
    const float* Pt = xyz + ((size_t)b * N_ + j) * 3;
    const float* Q  = g_newxyz + (size_t)bm * 3;
    float f0 = Pt[0] - Q[0], f1 = Pt[1] - Q[1], f2 = Pt[2] - Q[2];

    const float4* prow = (const float4*)(g_P + ((size_t)b * N_ + j) * 64);
    float acc[64];
    float4 a0 = __ldg(&prow[0]);
    float4 a1 = __ldg(&prow[1]);
    float4* yo = (float4*)g_Y1 + (size_t)blockIdx.x * 2048 + t;
#pragma unroll 1
    for (int kc = 0; kc < 16; kc++) {
        float4 pv = a0; a0 = a1;
        a1 = __ldg(&prow[(kc < 14) ? (kc + 2) : 15]);
        int o = kc * 4;
        float ss[4] = {pv.x, pv.y, pv.z, pv.w};
#pragma unroll
        for (int kk = 0; kk < 4; kk++) {
            float v = ss[kk];
            v = fmaf(f0, ws[o+kk],       v);
            v = fmaf(f1, ws[64 + o+kk],  v);
            v = fmaf(f2, ws[128 + o+kk], v);
            acc[o+kk] = v;
        }
        float4 st = {acc[o], acc[o+1], acc[o+2], acc[o+3]};
        yo[kc*128] = st;
    }
    __syncthreads();
    // deterministic per-block channel sums
#pragma unroll
    for (int o = 0; o < 64; o++) tile[t*65 + o] = acc[o];
    __syncthreads();
    int c = t & 63, g = t >> 6;
    float sa = 0.f, qa = 0.f;
#pragma unroll 4
    for (int rr = g*64; rr < g*64 + 64; rr++) {
        float v = tile[rr*65 + c];
        sa += v; qa = fmaf(v, v, qa);
    }
    ps[g*64 + c] = sa; pq[g*64 + c] = qa;
    __syncthreads();
    if (t < 64) {
        g_psum[(size_t)blockIdx.x*64 + t] = ps[t] + ps[64 + t];
        g_psq [(size_t)blockIdx.x*64 + t] = pq[t] + pq[64 + t];
    }
}

// ------------------------- layer 2: BN0+ReLU(Y1) @ W1 (f32x2, blocked) --------------------
__global__ __launch_bounds__(128)
void k_gemm2() {
    extern __shared__ __align__(16) float dyn[];
    float* ws   = dyn;            // union with tile
    float* tile = dyn;            // 8320 (used after sync)
    float* sc   = dyn + 8320;     // 64
    float* sh   = sc + 64;        // 64
    float* ps   = sh + 64;        // 128
    float* pq   = ps + 128;       // 128   total 8704 floats
    int t = threadIdx.x;
    for (int i = t; i < 4096; i += 128) ws[i] = g_wt1[i];
    if (t < 64) { sc[t] = g_scale[0][t]; sh[t] = g_shift[0][t]; }
    __syncthreads();

    const float4* xr = (const float4*)g_Y1 + (size_t)blockIdx.x * 2048 + t;
    ull acc2[32];
#pragma unroll
    for (int p = 0; p < 32; p++) acc2[p] = 0ull;

    float4 a0 = xr[0];
    float4 a1 = xr[128];
#pragma unroll 1
    for (int kc = 0; kc < 16; kc++) {
        float4 yv = a0; a0 = a1;
        a1 = xr[((kc < 14) ? (kc + 2) : 15) * 128];
        int kb = kc * 4;
        float ys[4] = {yv.x, yv.y, yv.z, yv.w};
#pragma unroll
        for (int kk = 0; kk < 4; kk++) {
            float xk = fmaxf(fmaf(ys[kk], sc[kb+kk], sh[kb+kk]), 0.f);
            ull xk2 = pk2(xk);
            const ulonglong2* wr = (const ulonglong2*)(ws + (kb+kk)*64);
#pragma unroll
            for (int p = 0; p < 16; p++) {
                ulonglong2 wv = wr[p];
                fma2(acc2[2*p],   xk2, wv.x);
                fma2(acc2[2*p+1], xk2, wv.y);
            }
        }
    }
    ulonglong2* yo = (ulonglong2*)((float4*)g_Y2 + (size_t)blockIdx.x * 2048 + t);
#pragma unroll
    for (int kc = 0; kc < 16; kc++)
        yo[kc*128] = make_ulonglong2(acc2[2*kc], acc2[2*kc+1]);

    __syncthreads();   // ws no longer needed; tile aliases it
#pragma unroll
    for (int p = 0; p < 32; p++) {
        float2 f = up2(acc2[p]);
        tile[t*65 + 2*p]     = f.x;
        tile[t*65 + 2*p + 1] = f.y;
    }
    __syncthreads();
    int c = t & 63, g = t >> 6;
    float sa = 0.f, qa = 0.f;
#pragma unroll 4
    for (int rr = g*64; rr < g*64 + 64; rr++) {
        float v = tile[rr*65 + c];
        sa += v; qa = fmaf(v, v, qa);
    }
    ps[g*64 + c] = sa; pq[g*64 + c] = qa;
    __syncthreads();
    if (t < 64) {
        g_psum[(size_t)blockIdx.x*64 + t] = ps[t] + ps[64 + t];
        g_psq [(size_t)blockIdx.x*64 + t] = pq[t] + pq[64 + t];
    }
}

// ------------------------- layer 3: BN1+ReLU(Y2) @ W2 -> 128 ch (f32x2) --------------------
__global__ __launch_bounds__(256)
void k_gemm3() {
    extern __shared__ __align__(16) float dyn[];
    float* ws   = dyn;             // union with tile
    float* tile = dyn;             // 16512
    float* sc   = dyn + 16512;     // 64
    float* sh   = sc + 64;         // 64
    float* ps   = sh + 64;         // 256
    float* pq   = ps + 256;        // 256   total 17152 floats
    int t = threadIdx.x;
    for (int i = t; i < 64*128; i += 256) ws[i] = g_wt2[i];
    if (t < 64) { sc[t] = g_scale[1][t]; sh[t] = g_shift[1][t]; }
    __syncthreads();

    int row  = t & 127;
    int half = (t >> 7) * 64;
    const float4* xr = (const float4*)g_Y2 + (size_t)blockIdx.x * 2048 + row;
    ull acc2[32];
#pragma unroll
    for (int p = 0; p < 32; p++) acc2[p] = 0ull;

    float4 a0 = xr[0];
    float4 a1 = xr[128];
#pragma unroll 1
    for (int kc = 0; kc < 16; kc++) {
        float4 yv = a0; a0 = a1;
        a1 = xr[((kc < 14) ? (kc + 2) : 15) * 128];
        int kb = kc * 4;
        float ys[4] = {yv.x, yv.y, yv.z, yv.w};
#pragma unroll
        for (int kk = 0; kk < 4; kk++) {
            float xk = fmaxf(fmaf(ys[kk], sc[kb+kk], sh[kb+kk]), 0.f);
            ull xk2 = pk2(xk);
            const ulonglong2* wr = (const ulonglong2*)(ws + (kb+kk)*128 + half);
#pragma unroll
            for (int p = 0; p < 16; p++) {
                ulonglong2 wv = wr[p];
                fma2(acc2[2*p],   xk2, wv.x);
                fma2(acc2[2*p+1], xk2, wv.y);
            }
        }
    }
    ulonglong2* yo = (ulonglong2*)((float4*)g_Y3 + (size_t)blockIdx.x * 4096
                                   + (size_t)(t >> 7) * 2048 + row);
#pragma unroll
    for (int kc = 0; kc < 16; kc++)
        yo[kc*128] = make_ulonglong2(acc2[2*kc], acc2[2*kc+1]);

    __syncthreads();   // ws done; tile aliases it
#pragma unroll
    for (int p = 0; p < 32; p++) {
        float2 f = up2(acc2[p]);
        tile[row*129 + half + 2*p]     = f.x;
        tile[row*129 + half + 2*p + 1] = f.y;
    }
    __syncthreads();
    int c = t & 127, g = t >> 7;
    float sa = 0.f, qa = 0.f;
#pragma unroll 4
    for (int rr = g*64; rr < g*64 + 64; rr++) {
        float v = tile[rr*129 + c];
        sa += v; qa = fmaf(v, v, qa);
    }
    ps[g*128 + c] = sa; pq[g*128 + c] = qa;
    __syncthreads();
    if (t < 128) {
        g_psum[(size_t)blockIdx.x*128 + t] = ps[t] + ps[128 + t];
        g_psq [(size_t)blockIdx.x*128 + t] = pq[t] + pq[128 + t];
    }
}

// ------------------------- finalize BN stats: one block per channel -----------------------
__global__ __launch_bounds__(256)
void k_fin(const float* __restrict__ gma, const float* __restrict__ beta,
           int OC, int layer) {
    int c = blockIdx.x, t = threadIdx.x;
    float s = 0.f, s2 = 0.f;
    for (int i = t; i < 4096; i += 256) {
        s  += g_psum[(size_t)i * OC + c];
        s2 += g_psq [(size_t)i * OC + c];
    }
#pragma unroll
    for (int off = 16; off; off >>= 1) {
        s  += __shfl_down_sync(0xffffffffu, s, off);
        s2 += __shfl_down_sync(0xffffffffu, s2, off);
    }
    __shared__ float a[8], a2[8];
    if ((t & 31) == 0) { a[t>>5] = s; a2[t>>5] = s2; }
    __syncthreads();
    if (t == 0) {
        double S = 0.0, S2 = 0.0;
#pragma unroll
        for (int wb = 0; wb < 8; wb++) { S += (double)a[wb]; S2 += (double)a2[wb]; }
        double inv  = 1.0 / (double)NROWS;
        double mean = S * inv;
        double var  = S2 * inv - mean * mean;
        float scale = (float)((double)gma[c] * rsqrt(var + 1e-5));
        float shift = (float)((double)beta[c] - mean * (double)scale);
        g_scale[layer][c] = scale;
        g_shift[layer][c] = shift;
    }
}

// ------------------------- BN2+ReLU(Y3) + max pool + transposed write ---------------------
__global__ __launch_bounds__(128)
void k_pool(float* __restrict__ out) {
    __shared__ float ssc[128], ssh[128];
    __shared__ float sm[4*128];
    int t = threadIdx.x;
    ssc[t] = g_scale[2][t]; ssh[t] = g_shift[2][t];
    __syncthreads();

    const float4* Y = (const float4*)g_Y3 + (size_t)blockIdx.x * 4096 + t;
    int w = t >> 5;
#pragma unroll 1
    for (int kc = 0; kc < 32; kc++) {
        float4 v = Y[kc*128];
        int ch = ((kc >> 4) << 6) + ((kc & 15) << 2);
        float m0 = fmaxf(fmaf(v.x, ssc[ch],   ssh[ch]),   0.f);
        float m1 = fmaxf(fmaf(v.y, ssc[ch+1], ssh[ch+1]), 0.f);
        float m2 = fmaxf(fmaf(v.z, ssc[ch+2], ssh[ch+2]), 0.f);
        float m3 = fmaxf(fmaf(v.w, ssc[ch+3], ssh[ch+3]), 0.f);
        unsigned r0 = __reduce_max_sync(0xffffffffu, __float_as_uint(m0));
        unsigned r1 = __reduce_max_sync(0xffffffffu, __float_as_uint(m1));
        unsigned r2 = __reduce_max_sync(0xffffffffu, __float_as_uint(m2));
        unsigned r3 = __reduce_max_sync(0xffffffffu, __float_as_uint(m3));
        if ((t & 31) == 0) {
            sm[w*128 + ch]   = __uint_as_float(r0);
            sm[w*128 + ch+1] = __uint_as_float(r1);
            sm[w*128 + ch+2] = __uint_as_float(r2);
            sm[w*128 + ch+3] = __uint_as_float(r3);
        }
    }
    __syncthreads();
    int q0 = blockIdx.x * 4;
    int b  = q0 >> 10;
#pragma unroll
    for (int qi = 0; qi < 4; qi++) {
        int m = (q0 + qi) & 1023;
        out[49152 + ((size_t)b * 128 + t) * 1024 + m] = sm[qi*128 + t];
    }
}

// ------------------------- launch --------------------------------------------------------
extern "C" void kernel_launch(void* const* d_in, const int* in_sizes, int n_in,
                              void* d_out, int out_size) {
    const float* xyz = (const float*)d_in[0];
    const float* pts = (const float*)d_in[1];
    const float* w0  = (const float*)d_in[2];
    const float* g0  = (const float*)d_in[4];
    const float* be0 = (const float*)d_in[5];
    const float* w1  = (const float*)d_in[6];
    const float* g1  = (const float*)d_in[8];
    const float* be1 = (const float*)d_in[9];
    const float* w2  = (const float*)d_in[10];
    const float* g2  = (const float*)d_in[12];
    const float* be2 = (const float*)d_in[13];
    float* out = (float*)d_out;

    const int SMEM2 = 8704 * 4;    // 34816 B
    const int SMEM3 = 17152 * 4;   // 68608 B
    cudaFuncSetAttribute(k_gemm2, cudaFuncAttributeMaxDynamicSharedMemorySize, SMEM2);
    cudaFuncSetAttribute(k_gemm3, cudaFuncAttributeMaxDynamicSharedMemorySize, SMEM3);

    k_init<<<64, 256>>>(w0, w1, w2);
    k_front<<<208, 1024>>>(xyz, pts, out);
    k_knn<<<B_*NP_, 128>>>();

    k_gemm1<<<NROWS/128, 128>>>(xyz);
    k_fin<<<64, 256>>>(g0, be0, 64, 0);

    k_gemm2<<<NROWS/128, 128, SMEM2>>>();
    k_fin<<<64, 256>>>(g1, be1, 64, 1);

    k_gemm3<<<NROWS/128, 256, SMEM3>>>();
    k_fin<<<128, 256>>>(g2, be2, 128, 2);

    k_pool<<<NROWS/128, 128>>>(out);
}

// round 10
// speedup vs baseline: 3.7278x; 1.0896x over previous
#include <cuda_runtime.h>
#include <math_constants.h>

#define B_   16
#define N_   4096
#define NP_  1024
#define NS_  32
#define NROWS 524288   // B_*NP_*NS_

typedef unsigned long long ull;

// ------------------------- static device scratch (no allocation) -------------------------
__device__ __align__(16) float g_newxyz[B_*NP_*3];
__device__ __align__(16) float4 g_xyzw[B_*N_];       // (x,y,z,sq)
__device__ int   g_knn[B_*NP_*NS_];
__device__ __align__(16) float g_P [4194304];    // 65536 x 64   pts @ W0[3:]
__device__ __align__(16) float g_Y1[33554432];   // blocked 4096 x 16 x 128 x 4
__device__ __align__(16) float g_Y2[33554432];   // blocked 4096 x 16 x 128 x 4
__device__ __align__(16) float g_Mx[B_*NP_*128]; // raw per-(query,ch) max of layer-3 out
__device__ __align__(16) float g_Mn[B_*NP_*128]; // raw per-(query,ch) min
__device__ float g_psum[4096*128];
__device__ float g_psq [4096*128];
__device__ float g_scale[3][128];
__device__ float g_shift[3][128];
__device__ __align__(16) float g_wt0[67*64];
__device__ __align__(16) float g_wt1[64*64];
__device__ __align__(16) float g_wt2[64*128];

// ------------------------- f32x2 packed helpers -------------------------
__device__ __forceinline__ void fma2(ull& d, ull a, ull b) {
    asm("fma.rn.f32x2 %0, %1, %2, %0;" : "+l"(d) : "l"(a), "l"(b));
}
__device__ __forceinline__ ull pk2(float x) {
    ull u;
    asm("mov.b64 %0, {%1, %2};" : "=l"(u) : "f"(x), "f"(x));
    return u;
}
__device__ __forceinline__ float2 up2(ull u) {
    float2 f;
    asm("mov.b64 {%0, %1}, %2;" : "=f"(f.x), "=f"(f.y) : "l"(u));
    return f;
}

// ------------------------- init: transpose weights to [K][OC] -------------------------
__global__ void k_init(const float* __restrict__ w0, const float* __restrict__ w1,
                       const float* __restrict__ w2) {
    int t = blockIdx.x * blockDim.x + threadIdx.x;
    int stride = gridDim.x * blockDim.x;
    for (int l = t; l < 64*67; l += stride) { int oc = l / 67, k = l - oc*67; g_wt0[k*64 + oc] = w0[l]; }
    for (int l = t; l < 64*64; l += stride) { int oc = l >> 6, k = l & 63;    g_wt1[k*64 + oc] = w1[l]; }
    for (int l = t; l < 128*64; l += stride){ int oc = l >> 6, k = l & 63;    g_wt2[k*128 + oc] = w2[l]; }
}

// ------------------------- fused front: P precompute | xyzw table | FPS -------------------
__global__ __launch_bounds__(1024)
void k_front(const float* __restrict__ xyz, const float* __restrict__ pts,
             float* __restrict__ out) {
    __shared__ __align__(16) float ws[4096];
    __shared__ unsigned sv[2][32]; __shared__ int si_[2][32];
    int blk = blockIdx.x, t = threadIdx.x;

    if (blk < 128) {
        // ---- P = pts @ W0[3:,:]
        for (int i = t; i < 4096; i += 1024) ws[i] = g_wt0[192 + i];
        __syncthreads();
        int row  = blk * 512 + (t >> 1);
        int half = (t & 1) * 32;
        const float4* xr = (const float4*)(pts + (size_t)row * 64);
        ull acc2[16];
#pragma unroll
        for (int p = 0; p < 16; p++) acc2[p] = 0ull;
        float4 a0 = __ldg(&xr[0]);
        float4 a1 = __ldg(&xr[1]);
#pragma unroll 1
        for (int kc = 0; kc < 16; kc++) {
            float4 xv = a0; a0 = a1;
            a1 = __ldg(&xr[(kc < 14) ? (kc + 2) : 15]);
            float xs[4] = {xv.x, xv.y, xv.z, xv.w};
#pragma unroll
            for (int kk = 0; kk < 4; kk++) {
                ull xk2 = pk2(xs[kk]);
                const ulonglong2* wr = (const ulonglong2*)(ws + (kc*4 + kk)*64 + half);
#pragma unroll
                for (int p = 0; p < 8; p++) {
                    ulonglong2 wv = wr[p];
                    fma2(acc2[p*2],   xk2, wv.x);
                    fma2(acc2[p*2+1], xk2, wv.y);
                }
            }
        }
        ulonglong2* po = (ulonglong2*)(g_P + (size_t)row * 64 + half);
#pragma unroll
        for (int p = 0; p < 8; p++) po[p] = make_ulonglong2(acc2[2*p], acc2[2*p+1]);
        return;
    }
    if (blk < 192) {
        int n = (blk - 128) * 1024 + t;
        const float* X = xyz + (size_t)n * 3;
        float x = X[0], y = X[1], z = X[2];
        float sq = __fadd_rn(__fadd_rn(__fmul_rn(x,x), __fmul_rn(y,y)), __fmul_rn(z,z));
        g_xyzw[n] = make_float4(x, y, z, sq);
        return;
    }

    // ---- FPS: single barrier per iteration (double-buffered winner slots)
    int b = blk - 192;
    int lane = t & 31, w = t >> 5;
    const float* X = xyz + (size_t)b * N_ * 3;
    float px[4], py[4], pz[4], dd[4];
#pragma unroll
    for (int j = 0; j < 4; j++) {
        int n = t*4 + j;
        px[j] = X[n*3]; py[j] = X[n*3+1]; pz[j] = X[n*3+2];
        dd[j] = 1e10f;
    }
    float ccx = X[0], ccy = X[1], ccz = X[2];
    float* nx = g_newxyz + (size_t)b * NP_ * 3;
    float* ox = out + (size_t)b * NP_ * 3;

    for (int i = 0; i < NP_; i++) {
        if (t == 0) {
            nx[i*3] = ccx; nx[i*3+1] = ccy; nx[i*3+2] = ccz;
            ox[i*3] = ccx; ox[i*3+1] = ccy; ox[i*3+2] = ccz;
        }
        float bv = -1.0f; int bi = 0;
#pragma unroll
        for (int j = 0; j < 4; j++) {
            float dx = __fsub_rn(px[j], ccx);
            float dy = __fsub_rn(py[j], ccy);
            float dz = __fsub_rn(pz[j], ccz);
            float d  = __fadd_rn(__fadd_rn(__fmul_rn(dx,dx), __fmul_rn(dy,dy)), __fmul_rn(dz,dz));
            dd[j] = fminf(dd[j], d);
            if (dd[j] > bv) { bv = dd[j]; bi = t*4 + j; }
        }
        unsigned kv   = __float_as_uint(bv);
        unsigned vmax = __reduce_max_sync(0xffffffffu, kv);
        unsigned cand = (kv == vmax) ? (unsigned)bi : 0xffffffffu;
        unsigned imin = __reduce_min_sync(0xffffffffu, cand);
        int p = i & 1;
        if (lane == 0) { sv[p][w] = vmax; si_[p][w] = (int)imin; }
        __syncthreads();
        unsigned kv2 = sv[p][lane];
        int      ii  = si_[p][lane];
        unsigned vm2 = __reduce_max_sync(0xffffffffu, kv2);
        unsigned c2  = (kv2 == vm2) ? (unsigned)ii : 0xffffffffu;
        unsigned win = __reduce_min_sync(0xffffffffu, c2);
        const float* Pp = X + (size_t)win * 3;
        ccx = Pp[0]; ccy = Pp[1]; ccz = Pp[2];
    }
}

__device__ __forceinline__ unsigned fkey(float v) {
    unsigned u = __float_as_uint(v);
    return u ^ (unsigned)(((int)u >> 31) | 0x80000000);
}

// ------------------------- kNN: histogram radix-select (one block / query) -----------------
__global__ __launch_bounds__(128)
void k_knn() {
    int q = blockIdx.x, b = q >> 10, t = threadIdx.x;
    int lane = t & 31, w = t >> 5;
    const float4* X4 = g_xyzw + (size_t)b * N_;
    const float* Q = g_newxyz + (size_t)q * 3;
    float qx = Q[0], qy = Q[1], qz = Q[2];
    float sqn = __fadd_rn(__fadd_rn(__fmul_rn(qx,qx), __fmul_rn(qy,qy)), __fmul_rn(qz,qz));

    unsigned key[32];
#pragma unroll
    for (int i = 0; i < 32; i++) {
        float4 v = __ldg(&X4[i*128 + t]);
        float dot = __fadd_rn(__fadd_rn(__fmul_rn(qx,v.x), __fmul_rn(qy,v.y)), __fmul_rn(qz,v.z));
        float d2  = __fsub_rn(__fadd_rn(sqn, v.w), __fmul_rn(2.0f, dot));
        key[i] = fkey(d2);
    }

    __shared__ unsigned hist[2048];
    __shared__ unsigned sw[4];
    __shared__ unsigned spiv[3];
    __shared__ unsigned candk[64];
    __shared__ int candi[64];
    __shared__ int candn;

    for (int j = t; j < 2048; j += 128) hist[j] = 0;
    if (t == 0) candn = 0;
    __syncthreads();
#pragma unroll
    for (int i = 0; i < 32; i++) atomicAdd(&hist[key[i] >> 21], 1u);
    __syncthreads();
    unsigned s = 0;
#pragma unroll
    for (int j = 0; j < 16; j++) s += hist[t*16 + j];
    unsigned inc = s;
#pragma unroll
    for (int o = 1; o < 32; o <<= 1) { unsigned nn = __shfl_up_sync(~0u, inc, o); if (lane >= o) inc += nn; }
    if (lane == 31) sw[w] = inc;
    __syncthreads();
    unsigned wbase = 0;
    for (int j = 0; j < w; j++) wbase += sw[j];
    unsigned base = wbase + inc - s;
    if (base < 32 && base + s >= 32) {
        unsigned cum = base;
#pragma unroll
        for (int j = 0; j < 16; j++) {
            unsigned c = hist[t*16 + j];
            if (cum + c >= 32) { spiv[0] = t*16 + j; spiv[1] = cum; spiv[2] = c; break; }
            cum += c;
        }
    }
    __syncthreads();
    unsigned pb1 = spiv[0];
    unsigned cb  = spiv[1];
    unsigned pc  = spiv[2];
    unsigned Kstar, width;

    if (pc > 64) {
        unsigned need2 = 32 - cb;
        for (int j = t; j < 2048; j += 128) hist[j] = 0;
        __syncthreads();
#pragma unroll
        for (int i = 0; i < 32; i++)
            if ((key[i] >> 21) == pb1) atomicAdd(&hist[(key[i] >> 10) & 2047], 1u);
        __syncthreads();
        s = 0;
#pragma unroll
        for (int j = 0; j < 16; j++) s += hist[t*16 + j];
        inc = s;
#pragma unroll
        for (int o = 1; o < 32; o <<= 1) { unsigned nn = __shfl_up_sync(~0u, inc, o); if (lane >= o) inc += nn; }
        if (lane == 31) sw[w] = inc;
        __syncthreads();
        wbase = 0;
        for (int j = 0; j < w; j++) wbase += sw[j];
        base = wbase + inc - s;
        if (base < need2 && base + s >= need2) {
            unsigned cum = base;
#pragma unroll
            for (int j = 0; j < 16; j++) {
                unsigned c = hist[t*16 + j];
                if (cum + c >= need2) { spiv[0] = t*16 + j; spiv[1] = cum; break; }
                cum += c;
            }
        }
        __syncthreads();
        Kstar = (pb1 << 21) | (spiv[0] << 10);
        width = 1u << 10;
        cb = cb + spiv[1];
        __syncthreads();
    } else {
        Kstar = pb1 << 21;
        width = 1u << 21;
    }

    int ct = 0;
#pragma unroll
    for (int i = 0; i < 32; i++) ct += (key[i] < Kstar);
    int inci = ct;
#pragma unroll
    for (int o = 1; o < 32; o <<= 1) { int nn = __shfl_up_sync(~0u, inci, o); if (lane >= o) inci += nn; }
    if (lane == 31) sw[w] = (unsigned)inci;
    __syncthreads();
    int wb = 0;
    for (int j = 0; j < w; j++) wb += (int)sw[j];
    int slot = wb + inci - ct;
    int* KO = g_knn + (size_t)q * NS_;
#pragma unroll
    for (int i = 0; i < 32; i++) {
        unsigned k = key[i];
        if (k < Kstar) { KO[slot++] = i*128 + t; }
        else if (k - Kstar < width) {
            int p = atomicAdd(&candn, 1);
            if (p < 64) { candk[p] = k; candi[p] = i*128 + t; }
        }
    }
    __syncthreads();
    int L = candn; if (L > 64) L = 64;
    int need = 32 - (int)cb;
    if (t < L) {
        unsigned mk = candk[t]; int mi = candi[t];
        int rank = 0;
        for (int j = 0; j < L; j++) {
            unsigned kj = candk[j];
            rank += (kj < mk) || (kj == mk && candi[j] < mi);
        }
        if (rank < need) KO[cb + rank] = mi;
    }
}

// ------------------------- layer 1: gather(P, MLP=16) + rel_xyz @ W0[:3] -------------------
__global__ __launch_bounds__(128)
void k_gemm1(const float* __restrict__ xyz) {
    __shared__ float ws[192];
    __shared__ float tile[128*65];
    __shared__ float ps[128], pq[128];
    int t = threadIdx.x;
    for (int i = t; i < 192; i += 128) ws[i] = g_wt0[i];
    __syncthreads();

    size_t r = (size_t)blockIdx.x * 128 + t;
    int b  = (int)(r >> 15);
    int bm = (int)(r >> 5);
    int j  = g_knn[r];
    const float* Pt = xyz + ((size_t)b * N_ + j) * 3;
    const float* Q  = g_newxyz + (size_t)bm * 3;
    float f0 = Pt[0] - Q[0], f1 = Pt[1] - Q[1], f2 = Pt[2] - Q[2];

    const float4* prow = (const float4*)(g_P + ((size_t)b * N_ + j) * 64);
    float4 pv[16];
#pragma unroll
    for (int kc = 0; kc < 16; kc++) pv[kc] = __ldg(&prow[kc]);   // 16 outstanding

    float4* yo = (float4*)g_Y1 + (size_t)blockIdx.x * 2048 + t;
#pragma unroll
    for (int kc = 0; kc < 16; kc++) {
        int o = kc * 4;
        float4 st;
        st.x = fmaf(f2, ws[128+o],   fmaf(f1, ws[64+o],   fmaf(f0, ws[o],   pv[kc].x)));
        st.y = fmaf(f2, ws[128+o+1], fmaf(f1, ws[64+o+1], fmaf(f0, ws[o+1], pv[kc].y)));
        st.z = fmaf(f2, ws[128+o+2], fmaf(f1, ws[64+o+2], fmaf(f0, ws[o+2], pv[kc].z)));
        st.w = fmaf(f2, ws[128+o+3], fmaf(f1, ws[64+o+3], fmaf(f0, ws[o+3], pv[kc].w)));
        yo[kc*128] = st;
        tile[t*65 + o]     = st.x;
        tile[t*65 + o + 1] = st.y;
        tile[t*65 + o + 2] = st.z;
        tile[t*65 + o + 3] = st.w;
    }
    __syncthreads();
    int c = t & 63, g = t >> 6;
    float sa = 0.f, qa = 0.f;
#pragma unroll 4
    for (int rr = g*64; rr < g*64 + 64; rr++) {
        float v = tile[rr*65 + c];
        sa += v; qa = fmaf(v, v, qa);
    }
    ps[g*64 + c] = sa; pq[g*64 + c] = qa;
    __syncthreads();
    if (t < 64) {
        g_psum[(size_t)blockIdx.x*64 + t] = ps[t] + ps[64 + t];
        g_psq [(size_t)blockIdx.x*64 + t] = pq[t] + pq[64 + t];
    }
}

// ------------------------- layer 2: BN0+ReLU(Y1) @ W1 (f32x2, blocked) --------------------
__global__ __launch_bounds__(128)
void k_gemm2() {
    extern __shared__ __align__(16) float dyn[];
    float* ws   = dyn;            // union with tile
    float* tile = dyn;            // 8320 (used after sync)
    float* sc   = dyn + 8320;     // 64
    float* sh   = sc + 64;        // 64
    float* ps   = sh + 64;        // 128
    float* pq   = ps + 128;       // 128   total 8704 floats
    int t = threadIdx.x;
    for (int i = t; i < 4096; i += 128) ws[i] = g_wt1[i];
    if (t < 64) { sc[t] = g_scale[0][t]; sh[t] = g_shift[0][t]; }
    __syncthreads();

    const float4* xr = (const float4*)g_Y1 + (size_t)blockIdx.x * 2048 + t;
    ull acc2[32];
#pragma unroll
    for (int p = 0; p < 32; p++) acc2[p] = 0ull;

    float4 a0 = xr[0];
    float4 a1 = xr[128];
#pragma unroll 1
    for (int kc = 0; kc < 16; kc++) {
        float4 yv = a0; a0 = a1;
        a1 = xr[((kc < 14) ? (kc + 2) : 15) * 128];
        int kb = kc * 4;
        float ys[4] = {yv.x, yv.y, yv.z, yv.w};
#pragma unroll
        for (int kk = 0; kk < 4; kk++) {
            float xk = fmaxf(fmaf(ys[kk], sc[kb+kk], sh[kb+kk]), 0.f);
            ull xk2 = pk2(xk);
            const ulonglong2* wr = (const ulonglong2*)(ws + (kb+kk)*64);
#pragma unroll
            for (int p = 0; p < 16; p++) {
                ulonglong2 wv = wr[p];
                fma2(acc2[2*p],   xk2, wv.x);
                fma2(acc2[2*p+1], xk2, wv.y);
            }
        }
    }
    ulonglong2* yo = (ulonglong2*)((float4*)g_Y2 + (size_t)blockIdx.x * 2048 + t);
#pragma unroll
    for (int kc = 0; kc < 16; kc++)
        yo[kc*128] = make_ulonglong2(acc2[2*kc], acc2[2*kc+1]);

    __syncthreads();
#pragma unroll
    for (int p = 0; p < 32; p++) {
        float2 f = up2(acc2[p]);
        tile[t*65 + 2*p]     = f.x;
        tile[t*65 + 2*p + 1] = f.y;
    }
    __syncthreads();
    int c = t & 63, g = t >> 6;
    float sa = 0.f, qa = 0.f;
#pragma unroll 4
    for (int rr = g*64; rr < g*64 + 64; rr++) {
        float v = tile[rr*65 + c];
        sa += v; qa = fmaf(v, v, qa);
    }
    ps[g*64 + c] = sa; pq[g*64 + c] = qa;
    __syncthreads();
    if (t < 64) {
        g_psum[(size_t)blockIdx.x*64 + t] = ps[t] + ps[64 + t];
        g_psq [(size_t)blockIdx.x*64 + t] = pq[t] + pq[64 + t];
    }
}

// --------- layer 3: BN1+ReLU(Y2) @ W2 -> 128 ch; NO Y3 store, per-query raw min/max --------
__global__ __launch_bounds__(256)
void k_gemm3() {
    extern __shared__ __align__(16) float dyn[];
    float* ws   = dyn;             // union with tile
    float* tile = dyn;             // 16512
    float* sc   = dyn + 16512;     // 64
    float* sh   = sc + 64;         // 64
    float* ps   = sh + 64;         // 256
    float* pq   = ps + 256;        // 256   total 17152 floats
    int t = threadIdx.x;
    for (int i = t; i < 64*128; i += 256) ws[i] = g_wt2[i];
    if (t < 64) { sc[t] = g_scale[1][t]; sh[t] = g_shift[1][t]; }
    __syncthreads();

    int row  = t & 127;
    int half = (t >> 7) * 64;
    const float4* xr = (const float4*)g_Y2 + (size_t)blockIdx.x * 2048 + row;
    ull acc2[32];
#pragma unroll
    for (int p = 0; p < 32; p++) acc2[p] = 0ull;

    float4 a0 = xr[0];
    float4 a1 = xr[128];
#pragma unroll 1
    for (int kc = 0; kc < 16; kc++) {
        float4 yv = a0; a0 = a1;
        a1 = xr[((kc < 14) ? (kc + 2) : 15) * 128];
        int kb = kc * 4;
        float ys[4] = {yv.x, yv.y, yv.z, yv.w};
#pragma unroll
        for (int kk = 0; kk < 4; kk++) {
            float xk = fmaxf(fmaf(ys[kk], sc[kb+kk], sh[kb+kk]), 0.f);
            ull xk2 = pk2(xk);
            const ulonglong2* wr = (const ulonglong2*)(ws + (kb+kk)*128 + half);
#pragma unroll
            for (int p = 0; p < 16; p++) {
                ulonglong2 wv = wr[p];
                fma2(acc2[2*p],   xk2, wv.x);
                fma2(acc2[2*p+1], xk2, wv.y);
            }
        }
    }

    __syncthreads();   // ws done; tile aliases it
#pragma unroll
    for (int p = 0; p < 32; p++) {
        float2 f = up2(acc2[p]);
        tile[row*129 + half + 2*p]     = f.x;
        tile[row*129 + half + 2*p + 1] = f.y;
    }
    __syncthreads();

    // per-channel sums
    int c = t & 127, g = t >> 7;
    float sa = 0.f, qa = 0.f;
#pragma unroll 4
    for (int rr = g*64; rr < g*64 + 64; rr++) {
        float v = tile[rr*129 + c];
        sa += v; qa = fmaf(v, v, qa);
    }
    ps[g*128 + c] = sa; pq[g*128 + c] = qa;

    // per-(query, channel) raw min/max over the 32-sample groups (block = 4 queries)
#pragma unroll
    for (int e = t; e < 512; e += 256) {
        int qi = e >> 7, ch = e & 127;
        int r0 = qi * 32;
        float mx = tile[r0*129 + ch], mn = mx;
#pragma unroll 4
        for (int rr = r0 + 1; rr < r0 + 32; rr++) {
            float v = tile[rr*129 + ch];
            mx = fmaxf(mx, v); mn = fminf(mn, v);
        }
        g_Mx[(size_t)blockIdx.x*512 + e] = mx;
        g_Mn[(size_t)blockIdx.x*512 + e] = mn;
    }
    __syncthreads();
    if (t < 128) {
        g_psum[(size_t)blockIdx.x*128 + t] = ps[t] + ps[128 + t];
        g_psq [(size_t)blockIdx.x*128 + t] = pq[t] + pq[128 + t];
    }
}

// ------------------------- finalize BN stats: one block per channel -----------------------
__global__ __launch_bounds__(256)
void k_fin(const float* __restrict__ gma, const float* __restrict__ beta,
           int OC, int layer) {
    int c = blockIdx.x, t = threadIdx.x;
    float s = 0.f, s2 = 0.f;
    for (int i = t; i < 4096; i += 256) {
        s  += g_psum[(size_t)i * OC + c];
        s2 += g_psq [(size_t)i * OC + c];
    }
#pragma unroll
    for (int off = 16; off; off >>= 1) {
        s  += __shfl_down_sync(0xffffffffu, s, off);
        s2 += __shfl_down_sync(0xffffffffu, s2, off);
    }
    __shared__ float a[8], a2[8];
    if ((t & 31) == 0) { a[t>>5] = s; a2[t>>5] = s2; }
    __syncthreads();
    if (t == 0) {
        double S = 0.0, S2 = 0.0;
#pragma unroll
        for (int wb = 0; wb < 8; wb++) { S += (double)a[wb]; S2 += (double)a2[wb]; }
        double inv  = 1.0 / (double)NROWS;
        double mean = S * inv;
        double var  = S2 * inv - mean * mean;
        float scale = (float)((double)gma[c] * rsqrt(var + 1e-5));
        float shift = (float)((double)beta[c] - mean * (double)scale);
        g_scale[layer][c] = scale;
        g_shift[layer][c] = shift;
    }
}

// ---------- pool: BN2 applied to raw min/max (monotone-exact) + transposed write -----------
__global__ __launch_bounds__(128)
void k_pool(float* __restrict__ out) {
    __shared__ float sm[128*33];
    int t = threadIdx.x;
    float sc = g_scale[2][t], sh = g_shift[2][t];
    int q0 = blockIdx.x * 32;
    int b  = q0 >> 10;
    const float* src = (sc > 0.f) ? g_Mx : g_Mn;
#pragma unroll 4
    for (int qi = 0; qi < 32; qi++) {
        float v = src[(size_t)(q0 + qi)*128 + t];
        sm[t*33 + qi] = fmaxf(fmaf(v, sc, sh), 0.f);
    }
    __syncthreads();
    int mloc = t & 31, og = t >> 5;
    int mg = q0 & 1023;
#pragma unroll
    for (int i = 0; i < 32; i++) {
        int oc = og + i*4;
        out[49152 + ((size_t)(b*128 + oc))*1024 + mg + mloc] = sm[oc*33 + mloc];
    }
}

// ------------------------- launch --------------------------------------------------------
extern "C" void kernel_launch(void* const* d_in, const int* in_sizes, int n_in,
                              void* d_out, int out_size) {
    const float* xyz = (const float*)d_in[0];
    const float* pts = (const float*)d_in[1];
    const float* w0  = (const float*)d_in[2];
    const float* g0  = (const float*)d_in[4];
    const float* be0 = (const float*)d_in[5];
    const float* w1  = (const float*)d_in[6];
    const float* g1  = (const float*)d_in[8];
    const float* be1 = (const float*)d_in[9];
    const float* w2  = (const float*)d_in[10];
    const float* g2  = (const float*)d_in[12];
    const float* be2 = (const float*)d_in[13];
    float* out = (float*)d_out;

    const int SMEM2 = 8704 * 4;    // 34816 B
    const int SMEM3 = 17152 * 4;   // 68608 B
    cudaFuncSetAttribute(k_gemm2, cudaFuncAttributeMaxDynamicSharedMemorySize, SMEM2);
    cudaFuncSetAttribute(k_gemm3, cudaFuncAttributeMaxDynamicSharedMemorySize, SMEM3);

    k_init<<<64, 256>>>(w0, w1, w2);
    k_front<<<208, 1024>>>(xyz, pts, out);
    k_knn<<<B_*NP_, 128>>>();

    k_gemm1<<<NROWS/128, 128>>>(xyz);
    k_fin<<<64, 256>>>(g0, be0, 64, 0);

    k_gemm2<<<NROWS/128, 128, SMEM2>>>();
    k_fin<<<64, 256>>>(g1, be1, 64, 1);

    k_gemm3<<<NROWS/128, 256, SMEM3>>>();
    k_fin<<<128, 256>>>(g2, be2, 128, 2);

    k_pool<<<B_*NP_/32, 128>>>(out);
}